// round 6
// baseline (speedup 1.0000x reference)
#include <cuda_runtime.h>
#include <cuda_bf16.h>
#include <cstdint>

#define N_OBJ 32
#define NFILT 16
#define RDIM 16
#define BATCH 32
#define NQ 512
#define NG 4960                  // C(32,3)
#define NCOL 512                 // BATCH * NFILT
#define OUT_ELEMS (NQ * NCOL)    // 262144
#define KP 14880                 // K' = 3*NG = 465 * 32 exactly
#define NSPLIT 15
#define ITERS 31                 // 465 / 15
#define BK 32
#define LDSW 40                  // smem row stride (halves); 80B rows, ldmatrix-safe
#define GCHUNK 248               // 4960 = 20 * 248

// ---------------- scratch (device globals) -----------------------------------
__device__ float         g_P  [BATCH * 9 * 1024 * 16];   // P[b][ac][i*32+j][f]
__device__ float         g_PT [3 * BATCH * 1024 * 16];   // transposed planes ac=3,6,7
__device__ float         g_E  [3 * BATCH * 1024 * 16];   // E01,E02,E12 [e][b][xy][f]
__device__ __nv_bfloat16 g_Wb [NQ   * KP];               // A' [q][k']
__device__ __nv_bfloat16 g_RCb[NCOL * KP];               // B' [col][k']
__device__ float         g_part[NSPLIT * OUT_ELEMS];
__device__ int4          g_idx[NG];

// ---------------- helpers ----------------------------------------------------
__device__ __forceinline__ uint32_t smem_u32(const void* p) {
    uint32_t a;
    asm("{ .reg .u64 t; cvta.to.shared.u64 t, %1; cvt.u32.u64 %0, t; }" : "=r"(a) : "l"(p));
    return a;
}
__device__ __forceinline__ void ldmx4(uint32_t r[4], uint32_t addr) {
    asm volatile("ldmatrix.sync.aligned.m8n8.x4.shared.b16 {%0,%1,%2,%3}, [%4];"
                 : "=r"(r[0]), "=r"(r[1]), "=r"(r[2]), "=r"(r[3]) : "r"(addr));
}
__device__ __forceinline__ void mma_bf16(float c[4], const uint32_t a[4],
                                         uint32_t b0, uint32_t b1) {
    asm volatile("mma.sync.aligned.m16n8k16.row.col.f32.bf16.bf16.f32 "
                 "{%0,%1,%2,%3}, {%4,%5,%6,%7}, {%8,%9}, {%0,%1,%2,%3};"
                 : "+f"(c[0]), "+f"(c[1]), "+f"(c[2]), "+f"(c[3])
                 : "r"(a[0]), "r"(a[1]), "r"(a[2]), "r"(a[3]), "r"(b0), "r"(b1));
}
#define CP_ASYNC16(dst, src) \
    asm volatile("cp.async.cg.shared.global [%0], [%1], 16;" :: "r"(dst), "l"(src) : "memory")
#define CP_COMMIT() asm volatile("cp.async.commit_group;" ::: "memory")
#define CP_WAIT(n)  asm volatile("cp.async.wait_group %0;" :: "n"(n) : "memory")

// ---------------- kernel 0: unrank C(32,3) -----------------------------------
__global__ void k_idx() {
    int g = blockIdx.x * blockDim.x + threadIdx.x;
    if (g >= NG) return;
    int r = g, i = 0;
    for (; i < 30; ++i) { int c = (31 - i) * (30 - i) / 2; if (r < c) break; r -= c; }
    int j = i + 1;
    for (; j < 31; ++j) { int c = 31 - j; if (r < c) break; r -= c; }
    g_idx[g] = make_int4(i, j, j + 1 + r, 0);
}

// ---------------- kernel P: pair conv  P[b][ac][ij][f] (+ PT for ac=3,6,7) ---
__global__ __launch_bounds__(256) void k_pairconv(const float* __restrict__ inputs,
                                                  const float* __restrict__ filters) {
    __shared__ float4 s_sf[3 * 16 * 4];      // [acl][d][f4]
    const int t = threadIdx.x;
    const int ac0 = blockIdx.y * 3;
#pragma unroll
    for (int u = 0; u < 3; ++u) {
        int idx = t + u * 256;               // < 768
        int acl = idx >> 8, r = idx & 255;
        int d = r >> 4, f = r & 15;
        ((float*)s_sf)[(acl * 16 + d) * 16 + f] =
            filters[(f * 9 + ac0 + acl) * 16 + d];
    }
    __syncthreads();

    const int cell = blockIdx.x * 256 + t;   // (b, ij) in [0, 32768)
    const float4* rv4 = (const float4*)(inputs + (long)cell * 16);
    float4 rv[4];
#pragma unroll
    for (int u = 0; u < 4; ++u) rv[u] = rv4[u];
    const float rs[16] = { rv[0].x, rv[0].y, rv[0].z, rv[0].w,
                           rv[1].x, rv[1].y, rv[1].z, rv[1].w,
                           rv[2].x, rv[2].y, rv[2].z, rv[2].w,
                           rv[3].x, rv[3].y, rv[3].z, rv[3].w };
    const int b = cell >> 10, ij = cell & 1023;
    const int ji = ((ij & 31) << 5) | (ij >> 5);

#pragma unroll
    for (int acl = 0; acl < 3; ++acl) {
        const int ac = ac0 + acl;
        float4 acc[4] = { {0,0,0,0}, {0,0,0,0}, {0,0,0,0}, {0,0,0,0} };
#pragma unroll
        for (int d = 0; d < 16; ++d) {
            float xv = rs[d];
#pragma unroll
            for (int f4 = 0; f4 < 4; ++f4) {
                float4 sf = s_sf[(acl * 16 + d) * 4 + f4];
                acc[f4].x += xv * sf.x; acc[f4].y += xv * sf.y;
                acc[f4].z += xv * sf.z; acc[f4].w += xv * sf.w;
            }
        }
        float4* dst = (float4*)(g_P + ((long)(b * 9 + ac) * 1024 + ij) * 16);
#pragma unroll
        for (int f4 = 0; f4 < 4; ++f4) dst[f4] = acc[f4];
        if (ac == 3 || ac == 6 || ac == 7) {
            const int tp = (ac == 3) ? 0 : (ac == 6) ? 1 : 2;
            float4* dt = (float4*)(g_PT + ((long)(tp * 32 + b) * 1024 + ji) * 16);
#pragma unroll
            for (int f4 = 0; f4 < 4; ++f4) dt[f4] = acc[f4];
        }
    }
}

// ---------------- kernel E: combine planes -----------------------------------
// E01[x,y]=P1[x,y]+P3[y,x]+P0[x,x]; E02=P2+P6^T+diag(P8,y); E12=P5+P7^T+diag(P4,x)
__global__ __launch_bounds__(256) void k_comb() {
    const int cell = blockIdx.x * 256 + threadIdx.x;   // 32768
    const int b = cell >> 10, ij = cell & 1023;
    const int i = ij >> 5, j = ij & 31;

    const float4* P = (const float4*)g_P;
    const float4* PT = (const float4*)g_PT;
    float4* E = (float4*)g_E;
    const long pb = (long)b * 9 * 1024 * 4;   // float4 units per b-slab
#pragma unroll
    for (int e = 0; e < 3; ++e) {
        const int ns = (e == 0) ? 1 : (e == 1) ? 2 : 5;     // straight plane
        const int nd = (e == 0) ? 0 : (e == 1) ? 8 : 4;     // diagonal plane
        const int dij = (e == 1) ? (j * 33) : (i * 33);     // diag index
        const float4* ps = P + pb + ((long)ns * 1024 + ij) * 4;
        const float4* pt = PT + ((long)(e * 32 + b) * 1024 + ij) * 4;
        const float4* pd = P + pb + ((long)nd * 1024 + dij) * 4;
        float4* out = E + ((long)(e * 32 + b) * 1024 + ij) * 4;
#pragma unroll
        for (int f4 = 0; f4 < 4; ++f4) {
            float4 a = ps[f4], c = pt[f4], d = pd[f4];
            out[f4] = make_float4(a.x + c.x + d.x, a.y + c.y + d.y,
                                  a.z + c.z + d.z, a.w + c.w + d.w);
        }
    }
}

// ---------------- kernel A: assemble rel_conv + split -> B' [col][k'] --------
__global__ __launch_bounds__(256) void k_rcasm() {
    __shared__ __nv_bfloat16 s_t[16][3 * GCHUNK];   // 16 rows x 744 bf16
    const int t = threadIdx.x;
    const int b = blockIdx.y, chunk = blockIdx.x;

    if (t < GCHUNK) {
        const int g = chunk * GCHUNK + t;
        const int4 id = g_idx[g];
        const float4* e01 = (const float4*)(g_E + ((long)(0 * 32 + b) * 1024 + id.x * 32 + id.y) * 16);
        const float4* e02 = (const float4*)(g_E + ((long)(1 * 32 + b) * 1024 + id.x * 32 + id.z) * 16);
        const float4* e12 = (const float4*)(g_E + ((long)(2 * 32 + b) * 1024 + id.y * 32 + id.z) * 16);
        float4 acc[4];
#pragma unroll
        for (int f4 = 0; f4 < 4; ++f4) {
            float4 a = e01[f4], c = e02[f4], d = e12[f4];
            acc[f4] = make_float4(a.x + c.x + d.x, a.y + c.y + d.y,
                                  a.z + c.z + d.z, a.w + c.w + d.w);
        }
        const float* af = (const float*)acc;
#pragma unroll
        for (int f = 0; f < 16; ++f) {
            float x = af[f];
            __nv_bfloat16 hi = __float2bfloat16(x);
            __nv_bfloat16 lo = __float2bfloat16(x - __bfloat162float(hi));
            s_t[f][3 * t]     = hi;
            s_t[f][3 * t + 1] = lo;
            s_t[f][3 * t + 2] = hi;
        }
    }
    __syncthreads();

#pragma unroll 1
    for (int r = 0; r < 16; ++r) {
        const uint32_t* src = (const uint32_t*)&s_t[r][0];
        uint32_t* dst = (uint32_t*)(g_RCb + (long)(b * 16 + r) * KP + chunk * (3 * GCHUNK));
        for (int idx = t; idx < (3 * GCHUNK) / 2; idx += 256) dst[idx] = src[idx];
    }
}

// ---------------- kernel B: weights -> A' triple [wh, wh, wl] ----------------
__global__ __launch_bounds__(512) void k_weights(const float* __restrict__ logits) {
    __shared__ float s_sp[N_OBJ];
    __shared__ float s_w[NG];
    __shared__ float s_red[16];
    const int q = blockIdx.x;
    const int t = threadIdx.x;

    if (t < N_OBJ) {
        float x = logits[q * N_OBJ + t];
        s_sp[t] = fmaxf(x, 0.f) + log1pf(expf(-fabsf(x)));
    }
    __syncthreads();

    float lmax = -1e30f;
    for (int g = t; g < NG; g += 512) {
        int4 id = g_idx[g];
        float w = s_sp[id.x] * s_sp[id.y] * s_sp[id.z];
        s_w[g] = w;
        lmax = fmaxf(lmax, w);
    }
#pragma unroll
    for (int o = 16; o; o >>= 1) lmax = fmaxf(lmax, __shfl_xor_sync(0xFFFFFFFFu, lmax, o));
    if ((t & 31) == 0) s_red[t >> 5] = lmax;
    __syncthreads();
    float bmax = s_red[0];
#pragma unroll
    for (int w = 1; w < 16; ++w) bmax = fmaxf(bmax, s_red[w]);
    __syncthreads();

    float lsum = 0.f;
    for (int g = t; g < NG; g += 512) {
        float e = __expf(s_w[g] - bmax);
        s_w[g] = e;
        lsum += e;
    }
#pragma unroll
    for (int o = 16; o; o >>= 1) lsum += __shfl_xor_sync(0xFFFFFFFFu, lsum, o);
    if ((t & 31) == 0) s_red[t >> 5] = lsum;
    __syncthreads();
    float bsum = 0.f;
#pragma unroll
    for (int w = 0; w < 16; ++w) bsum += s_red[w];
    float inv = 1.0f / bsum;
    __syncthreads();

    // packed coalesced store: 2 g per thread -> 3 u32 words
    uint32_t* dst = (uint32_t*)(g_Wb + (long)q * KP);
    for (int g2 = t; g2 < NG / 2; g2 += 512) {
        float w0 = s_w[2 * g2] * inv, w1 = s_w[2 * g2 + 1] * inv;
        __nv_bfloat16 h0b = __float2bfloat16(w0);
        __nv_bfloat16 h1b = __float2bfloat16(w1);
        uint32_t h0 = __bfloat16_as_ushort(h0b);
        uint32_t l0 = __bfloat16_as_ushort(__float2bfloat16(w0 - __bfloat162float(h0b)));
        uint32_t h1 = __bfloat16_as_ushort(h1b);
        uint32_t l1 = __bfloat16_as_ushort(__float2bfloat16(w1 - __bfloat162float(h1b)));
        dst[3 * g2]     = h0 | (h0 << 16);
        dst[3 * g2 + 1] = l0 | (h1 << 16);
        dst[3 * g2 + 2] = h1 | (l1 << 16);
    }
}

// ---------------- kernel C: bf16 HMMA GEMM, cp.async double-buffered ---------
// 512x512xKP, split-K=15 (31 iters). BM=BN=128, BK=32, 8 warps 2(m)x4(n).
__global__ __launch_bounds__(256, 2) void k_mma() {
    __shared__ __align__(16) __nv_bfloat16 sA[2][128 * LDSW];
    __shared__ __align__(16) __nv_bfloat16 sB[2][128 * LDSW];
    const int t = threadIdx.x, lane = t & 31, wid = t >> 5;
    const int wm = wid & 1, wn = wid >> 1;
    const int m0 = blockIdx.y * 128, n0 = blockIdx.x * 128;
    const long kbase = (long)blockIdx.z * ITERS * BK;

    float acc[4][4][4];
#pragma unroll
    for (int i = 0; i < 4; ++i)
#pragma unroll
        for (int j = 0; j < 4; ++j)
#pragma unroll
            for (int v = 0; v < 4; ++v) acc[i][j][v] = 0.f;

    const int grow = t >> 2, gq = t & 3;
    const uint32_t sA0 = smem_u32(sA), sB0 = smem_u32(sB);
    const uint32_t BUFB = 128 * LDSW * 2;
    const uint32_t dA0 = sA0 + (uint32_t)((grow * LDSW + gq * 8) * 2);
    const uint32_t dA1 = dA0 + (uint32_t)(64 * LDSW * 2);
    const uint32_t dB0 = sB0 + (uint32_t)((grow * LDSW + gq * 8) * 2);
    const uint32_t dB1 = dB0 + (uint32_t)(64 * LDSW * 2);

    const int lr = lane & 15, lh = lane >> 4;
    const uint32_t aBase = sA0 + (uint32_t)(((wm * 64 + lr) * LDSW + lh * 8) * 2);
    const uint32_t bBase = sB0 + (uint32_t)(((wn * 32 + lr) * LDSW + lh * 8) * 2);

    {
        const long k0 = kbase;
        CP_ASYNC16(dA0, g_Wb  + (long)(m0 + grow)      * KP + k0 + gq * 8);
        CP_ASYNC16(dA1, g_Wb  + (long)(m0 + grow + 64) * KP + k0 + gq * 8);
        CP_ASYNC16(dB0, g_RCb + (long)(n0 + grow)      * KP + k0 + gq * 8);
        CP_ASYNC16(dB1, g_RCb + (long)(n0 + grow + 64) * KP + k0 + gq * 8);
        CP_COMMIT();
    }

#pragma unroll 1
    for (int tt = 0; tt < ITERS; ++tt) {
        if (tt + 1 < ITERS) {
            const long k0 = kbase + (long)(tt + 1) * BK;
            const uint32_t bo = ((tt + 1) & 1) * BUFB;
            CP_ASYNC16(dA0 + bo, g_Wb  + (long)(m0 + grow)      * KP + k0 + gq * 8);
            CP_ASYNC16(dA1 + bo, g_Wb  + (long)(m0 + grow + 64) * KP + k0 + gq * 8);
            CP_ASYNC16(dB0 + bo, g_RCb + (long)(n0 + grow)      * KP + k0 + gq * 8);
            CP_ASYNC16(dB1 + bo, g_RCb + (long)(n0 + grow + 64) * KP + k0 + gq * 8);
            CP_COMMIT();
            CP_WAIT(1);
        } else {
            CP_WAIT(0);
        }
        __syncthreads();

        const uint32_t bo = (tt & 1) * BUFB;
#pragma unroll
        for (int ks = 0; ks < 2; ++ks) {
            uint32_t af[4][4], bf[2][4];
#pragma unroll
            for (int mt = 0; mt < 4; ++mt)
                ldmx4(af[mt], aBase + bo + mt * (16 * LDSW * 2) + ks * 32);
#pragma unroll
            for (int np = 0; np < 2; ++np)
                ldmx4(bf[np], bBase + bo + np * (16 * LDSW * 2) + ks * 32);
#pragma unroll
            for (int mt = 0; mt < 4; ++mt)
#pragma unroll
                for (int nt = 0; nt < 4; ++nt)
                    mma_bf16(acc[mt][nt], af[mt], bf[nt >> 1][nt & 1],
                             bf[nt >> 1][(nt & 1) + 2]);
        }
        __syncthreads();
    }

    float* P = g_part + (long)blockIdx.z * OUT_ELEMS;
    const int erow = lane >> 2, ecol = (lane & 3) * 2;
#pragma unroll
    for (int mt = 0; mt < 4; ++mt)
#pragma unroll
        for (int nt = 0; nt < 4; ++nt) {
            int m = m0 + wm * 64 + mt * 16 + erow;
            int n = n0 + wn * 32 + nt * 8 + ecol;
            *(float2*)&P[(long)m * NCOL + n]       = make_float2(acc[mt][nt][0], acc[mt][nt][1]);
            *(float2*)&P[(long)(m + 8) * NCOL + n] = make_float2(acc[mt][nt][2], acc[mt][nt][3]);
        }
}

// ---------------- kernel D: reduce split-K partials + scatter ----------------
__global__ void k_reduce(float* __restrict__ out) {
    int t = blockIdx.x * blockDim.x + threadIdx.x;
    if (t >= OUT_ELEMS) return;
    float s = 0.f;
#pragma unroll
    for (int j = 0; j < NSPLIT; ++j)
        s += g_part[(long)j * OUT_ELEMS + t];
    int q = t >> 9, col = t & 511;
    int b = col >> 4, f = col & 15;
    out[(b * NQ + q) * NFILT + f] = s;   // out[b][q][f]
}

// ---------------- launch -----------------------------------------------------
extern "C" void kernel_launch(void* const* d_in, const int* in_sizes, int n_in,
                              void* d_out, int out_size) {
    const float *inputs = nullptr, *logits = nullptr, *filts = nullptr;
    for (int i = 0; i < n_in; ++i) {
        if (in_sizes[i] == BATCH * N_OBJ * N_OBJ * RDIM) inputs = (const float*)d_in[i];
        else if (in_sizes[i] == NQ * N_OBJ)              logits = (const float*)d_in[i];
        else if (in_sizes[i] == NFILT * 3 * 3 * RDIM)    filts = (const float*)d_in[i];
    }
    float* out = (float*)d_out;

    k_idx<<<20, 256>>>();
    k_pairconv<<<dim3(128, 3), 256>>>(inputs, filts);
    k_weights<<<NQ, 512>>>(logits);
    k_comb<<<128, 256>>>();
    k_rcasm<<<dim3(20, 32), 256>>>();
    k_mma<<<dim3(4, 4, NSPLIT), 256>>>();
    k_reduce<<<(OUT_ELEMS + 511) / 512, 512>>>(out);
}

// round 10
// speedup vs baseline: 1.5013x; 1.5013x over previous
#include <cuda_runtime.h>
#include <cuda_bf16.h>
#include <cstdint>

#define N_OBJ 32
#define NFILT 16
#define RDIM 16
#define BATCH 32
#define NQ 512
#define NG 4960                  // C(32,3)
#define NCOL 512                 // BATCH * NFILT
#define OUT_ELEMS (NQ * NCOL)    // 262144
#define KP 14880                 // K' = 3*NG = 465 * 32 exactly
#define NSPLIT 31
#define ITERS 15                 // 465 / 31
#define BK 32
#define LDSW 40                  // smem row stride (halves); 80B rows, ldmatrix-safe
#define GCHUNK 248               // 4960 = 20 * 248

// ---------------- scratch (device globals) -----------------------------------
__device__ float         g_P  [BATCH * 9 * 1024 * 16];   // P[b][ac][i*32+j][f]
__device__ float         g_E  [3 * BATCH * 1024 * 16];   // E01,E02,E12 [e][b][xy][f]
__device__ __nv_bfloat16 g_Wb [NQ   * KP];               // A' [q][k']
__device__ __nv_bfloat16 g_RCb[NCOL * KP];               // B' [col][k']
__device__ float         g_part[NSPLIT * OUT_ELEMS];
__device__ int4          g_idx[NG];

// ---------------- helpers ----------------------------------------------------
__device__ __forceinline__ uint32_t smem_u32(const void* p) {
    uint32_t a;
    asm("{ .reg .u64 t; cvta.to.shared.u64 t, %1; cvt.u32.u64 %0, t; }" : "=r"(a) : "l"(p));
    return a;
}
__device__ __forceinline__ void ldmx4(uint32_t r[4], uint32_t addr) {
    asm volatile("ldmatrix.sync.aligned.m8n8.x4.shared.b16 {%0,%1,%2,%3}, [%4];"
                 : "=r"(r[0]), "=r"(r[1]), "=r"(r[2]), "=r"(r[3]) : "r"(addr));
}
__device__ __forceinline__ void mma_bf16(float c[4], const uint32_t a[4],
                                         uint32_t b0, uint32_t b1) {
    asm volatile("mma.sync.aligned.m16n8k16.row.col.f32.bf16.bf16.f32 "
                 "{%0,%1,%2,%3}, {%4,%5,%6,%7}, {%8,%9}, {%0,%1,%2,%3};"
                 : "+f"(c[0]), "+f"(c[1]), "+f"(c[2]), "+f"(c[3])
                 : "r"(a[0]), "r"(a[1]), "r"(a[2]), "r"(a[3]), "r"(b0), "r"(b1));
}
#define CP_ASYNC16(dst, src) \
    asm volatile("cp.async.cg.shared.global [%0], [%1], 16;" :: "r"(dst), "l"(src) : "memory")
#define CP_COMMIT() asm volatile("cp.async.commit_group;" ::: "memory")
#define CP_WAIT(n)  asm volatile("cp.async.wait_group %0;" :: "n"(n) : "memory")

// ---------------- kernel 0: unrank C(32,3) -----------------------------------
__global__ void k_idx() {
    int g = blockIdx.x * blockDim.x + threadIdx.x;
    if (g >= NG) return;
    int r = g, i = 0;
    for (; i < 30; ++i) { int c = (31 - i) * (30 - i) / 2; if (r < c) break; r -= c; }
    int j = i + 1;
    for (; j < 31; ++j) { int c = 31 - j; if (r < c) break; r -= c; }
    g_idx[g] = make_int4(i, j, j + 1 + r, 0);
}

// ---------------- kernel P: pair conv  P[b][ac][ij][f] -----------------------
__global__ __launch_bounds__(256) void k_pairconv(const float* __restrict__ inputs,
                                                  const float* __restrict__ filters) {
    __shared__ float4 s_sf[3 * 16 * 4];      // [acl][d][f4]
    const int t = threadIdx.x;
    const int ac0 = blockIdx.y * 3;
#pragma unroll
    for (int u = 0; u < 3; ++u) {
        int idx = t + u * 256;               // < 768
        int acl = idx >> 8, r = idx & 255;
        int d = r >> 4, f = r & 15;
        ((float*)s_sf)[(acl * 16 + d) * 16 + f] =
            filters[(f * 9 + ac0 + acl) * 16 + d];
    }
    __syncthreads();

    const int cell = blockIdx.x * 256 + t;   // (b, ij) in [0, 32768)
    const float4* rv4 = (const float4*)(inputs + (long)cell * 16);
    float4 rv[4];
#pragma unroll
    for (int u = 0; u < 4; ++u) rv[u] = rv4[u];
    const float rs[16] = { rv[0].x, rv[0].y, rv[0].z, rv[0].w,
                           rv[1].x, rv[1].y, rv[1].z, rv[1].w,
                           rv[2].x, rv[2].y, rv[2].z, rv[2].w,
                           rv[3].x, rv[3].y, rv[3].z, rv[3].w };
    const int b = cell >> 10, ij = cell & 1023;

#pragma unroll
    for (int acl = 0; acl < 3; ++acl) {
        float4 acc[4] = { {0,0,0,0}, {0,0,0,0}, {0,0,0,0}, {0,0,0,0} };
#pragma unroll
        for (int d = 0; d < 16; ++d) {
            float xv = rs[d];
#pragma unroll
            for (int f4 = 0; f4 < 4; ++f4) {
                float4 sf = s_sf[(acl * 16 + d) * 4 + f4];
                acc[f4].x += xv * sf.x; acc[f4].y += xv * sf.y;
                acc[f4].z += xv * sf.z; acc[f4].w += xv * sf.w;
            }
        }
        float4* dst = (float4*)(g_P + ((long)(b * 9 + ac0 + acl) * 1024 + ij) * 16);
#pragma unroll
        for (int f4 = 0; f4 < 4; ++f4) dst[f4] = acc[f4];
    }
}

// ---------------- kernel E: combine planes (parallel over e,b,ij,f4) ---------
// E01[x,y]=P1[x,y]+P3[y,x]+P0[x,x]
// E02[x,y]=P2[x,y]+P6[y,x]+P8[y,y]
// E12[x,y]=P5[x,y]+P7[y,x]+P4[x,x]
__global__ __launch_bounds__(256) void k_comb() {
    const int tid = blockIdx.x * 256 + threadIdx.x;   // < 393216
    const int f4 = tid & 3;
    const int cell = tid >> 2;                         // (e,b,ij)
    const int ij = cell & 1023;
    const int b = (cell >> 10) & 31;
    const int e = cell >> 15;
    const int x = ij >> 5, y = ij & 31;

    const int ns = (e == 0) ? 1 : (e == 1) ? 2 : 5;    // straight plane
    const int nt = (e == 0) ? 3 : (e == 1) ? 6 : 7;    // transposed plane
    const int nd = (e == 0) ? 0 : (e == 1) ? 8 : 4;    // diagonal plane
    const int dij = (e == 1) ? (y * 33) : (x * 33);
    const int ji = (y << 5) | x;

    const long pb = (long)b * 9 * 1024 * 4;            // float4 units per b-slab
    const float4* P = (const float4*)g_P;
    float4 a = P[pb + ((long)ns * 1024 + ij) * 4 + f4];
    float4 c = P[pb + ((long)nt * 1024 + ji) * 4 + f4];
    float4 d = P[pb + ((long)nd * 1024 + dij) * 4 + f4];
    ((float4*)g_E)[((long)(e * 32 + b) * 1024 + ij) * 4 + f4] =
        make_float4(a.x + c.x + d.x, a.y + c.y + d.y,
                    a.z + c.z + d.z, a.w + c.w + d.w);
}

// ---------------- kernel A: assemble rel_conv + split -> B' [col][k'] --------
__global__ __launch_bounds__(256) void k_rcasm() {
    __shared__ __nv_bfloat16 s_t[16][3 * GCHUNK];   // 16 rows x 744 bf16
    const int t = threadIdx.x;
    const int b = blockIdx.y, chunk = blockIdx.x;

    if (t < GCHUNK) {
        const int g = chunk * GCHUNK + t;
        const int4 id = g_idx[g];
        const float4* e01 = (const float4*)(g_E + ((long)(0 * 32 + b) * 1024 + id.x * 32 + id.y) * 16);
        const float4* e02 = (const float4*)(g_E + ((long)(1 * 32 + b) * 1024 + id.x * 32 + id.z) * 16);
        const float4* e12 = (const float4*)(g_E + ((long)(2 * 32 + b) * 1024 + id.y * 32 + id.z) * 16);
        float4 acc[4];
#pragma unroll
        for (int f4 = 0; f4 < 4; ++f4) {
            float4 a = e01[f4], c = e02[f4], d = e12[f4];
            acc[f4] = make_float4(a.x + c.x + d.x, a.y + c.y + d.y,
                                  a.z + c.z + d.z, a.w + c.w + d.w);
        }
        const float* af = (const float*)acc;
#pragma unroll
        for (int f = 0; f < 16; ++f) {
            float x = af[f];
            __nv_bfloat16 hi = __float2bfloat16(x);
            __nv_bfloat16 lo = __float2bfloat16(x - __bfloat162float(hi));
            s_t[f][3 * t]     = hi;
            s_t[f][3 * t + 1] = lo;
            s_t[f][3 * t + 2] = hi;
        }
    }
    __syncthreads();

#pragma unroll 1
    for (int r = 0; r < 16; ++r) {
        const uint32_t* src = (const uint32_t*)&s_t[r][0];
        uint32_t* dst = (uint32_t*)(g_RCb + (long)(b * 16 + r) * KP + chunk * (3 * GCHUNK));
        for (int idx = t; idx < (3 * GCHUNK) / 2; idx += 256) dst[idx] = src[idx];
    }
}

// ---------------- kernel B: weights -> A' triple [wh, wh, wl] ----------------
__global__ __launch_bounds__(256) void k_weights(const float* __restrict__ logits) {
    __shared__ float s_sp[N_OBJ];
    __shared__ float s_w[NG];
    __shared__ float s_red[8];
    const int q = blockIdx.x;
    const int t = threadIdx.x;

    if (t < N_OBJ) {
        float x = logits[q * N_OBJ + t];
        s_sp[t] = fmaxf(x, 0.f) + log1pf(expf(-fabsf(x)));
    }
    __syncthreads();

    float lmax = -1e30f;
    for (int g = t; g < NG; g += 256) {
        int4 id = g_idx[g];
        float w = s_sp[id.x] * s_sp[id.y] * s_sp[id.z];
        s_w[g] = w;
        lmax = fmaxf(lmax, w);
    }
#pragma unroll
    for (int o = 16; o; o >>= 1) lmax = fmaxf(lmax, __shfl_xor_sync(0xFFFFFFFFu, lmax, o));
    if ((t & 31) == 0) s_red[t >> 5] = lmax;
    __syncthreads();
    float bmax = s_red[0];
#pragma unroll
    for (int w = 1; w < 8; ++w) bmax = fmaxf(bmax, s_red[w]);
    __syncthreads();

    float lsum = 0.f;
    for (int g = t; g < NG; g += 256) {
        float e = __expf(s_w[g] - bmax);
        s_w[g] = e;
        lsum += e;
    }
#pragma unroll
    for (int o = 16; o; o >>= 1) lsum += __shfl_xor_sync(0xFFFFFFFFu, lsum, o);
    if ((t & 31) == 0) s_red[t >> 5] = lsum;
    __syncthreads();
    float bsum = 0.f;
#pragma unroll
    for (int w = 0; w < 8; ++w) bsum += s_red[w];
    float inv = 1.0f / bsum;

    for (int g = t; g < NG; g += 256) {
        float w = s_w[g] * inv;
        __nv_bfloat16 hi = __float2bfloat16(w);
        __nv_bfloat16 lo = __float2bfloat16(w - __bfloat162float(hi));
        __nv_bfloat16* dst = g_Wb + (long)q * KP + 3 * g;
        dst[0] = hi; dst[1] = hi; dst[2] = lo;
    }
}

// ---------------- kernel C: bf16 HMMA GEMM, cp.async double-buffered ---------
// 512x512xKP, split-K=31 (15 iters). BM=BN=128, BK=32, 8 warps 2(m)x4(n).
__global__ __launch_bounds__(256, 2) void k_mma() {
    __shared__ __align__(16) __nv_bfloat16 sA[2][128 * LDSW];
    __shared__ __align__(16) __nv_bfloat16 sB[2][128 * LDSW];
    const int t = threadIdx.x, lane = t & 31, wid = t >> 5;
    const int wm = wid & 1, wn = wid >> 1;
    const int m0 = blockIdx.y * 128, n0 = blockIdx.x * 128;
    const long kbase = (long)blockIdx.z * ITERS * BK;

    float acc[4][4][4];
#pragma unroll
    for (int i = 0; i < 4; ++i)
#pragma unroll
        for (int j = 0; j < 4; ++j)
#pragma unroll
            for (int v = 0; v < 4; ++v) acc[i][j][v] = 0.f;

    const int grow = t >> 2, gq = t & 3;
    const uint32_t sA0 = smem_u32(sA), sB0 = smem_u32(sB);
    const uint32_t BUFB = 128 * LDSW * 2;
    const uint32_t dA0 = sA0 + (uint32_t)((grow * LDSW + gq * 8) * 2);
    const uint32_t dA1 = dA0 + (uint32_t)(64 * LDSW * 2);
    const uint32_t dB0 = sB0 + (uint32_t)((grow * LDSW + gq * 8) * 2);
    const uint32_t dB1 = dB0 + (uint32_t)(64 * LDSW * 2);

    const int lr = lane & 15, lh = lane >> 4;
    const uint32_t aBase = sA0 + (uint32_t)(((wm * 64 + lr) * LDSW + lh * 8) * 2);
    const uint32_t bBase = sB0 + (uint32_t)(((wn * 32 + lr) * LDSW + lh * 8) * 2);

    {
        const long k0 = kbase;
        CP_ASYNC16(dA0, g_Wb  + (long)(m0 + grow)      * KP + k0 + gq * 8);
        CP_ASYNC16(dA1, g_Wb  + (long)(m0 + grow + 64) * KP + k0 + gq * 8);
        CP_ASYNC16(dB0, g_RCb + (long)(n0 + grow)      * KP + k0 + gq * 8);
        CP_ASYNC16(dB1, g_RCb + (long)(n0 + grow + 64) * KP + k0 + gq * 8);
        CP_COMMIT();
    }

#pragma unroll 1
    for (int tt = 0; tt < ITERS; ++tt) {
        if (tt + 1 < ITERS) {
            const long k0 = kbase + (long)(tt + 1) * BK;
            const uint32_t bo = ((tt + 1) & 1) * BUFB;
            CP_ASYNC16(dA0 + bo, g_Wb  + (long)(m0 + grow)      * KP + k0 + gq * 8);
            CP_ASYNC16(dA1 + bo, g_Wb  + (long)(m0 + grow + 64) * KP + k0 + gq * 8);
            CP_ASYNC16(dB0 + bo, g_RCb + (long)(n0 + grow)      * KP + k0 + gq * 8);
            CP_ASYNC16(dB1 + bo, g_RCb + (long)(n0 + grow + 64) * KP + k0 + gq * 8);
            CP_COMMIT();
            CP_WAIT(1);
        } else {
            CP_WAIT(0);
        }
        __syncthreads();

        const uint32_t bo = (tt & 1) * BUFB;
#pragma unroll
        for (int ks = 0; ks < 2; ++ks) {
            uint32_t af[4][4], bf[2][4];
#pragma unroll
            for (int mt = 0; mt < 4; ++mt)
                ldmx4(af[mt], aBase + bo + mt * (16 * LDSW * 2) + ks * 32);
#pragma unroll
            for (int np = 0; np < 2; ++np)
                ldmx4(bf[np], bBase + bo + np * (16 * LDSW * 2) + ks * 32);
#pragma unroll
            for (int mt = 0; mt < 4; ++mt)
#pragma unroll
                for (int nt = 0; nt < 4; ++nt)
                    mma_bf16(acc[mt][nt], af[mt], bf[nt >> 1][nt & 1],
                             bf[nt >> 1][(nt & 1) + 2]);
        }
        __syncthreads();
    }

    float* P = g_part + (long)blockIdx.z * OUT_ELEMS;
    const int erow = lane >> 2, ecol = (lane & 3) * 2;
#pragma unroll
    for (int mt = 0; mt < 4; ++mt)
#pragma unroll
        for (int nt = 0; nt < 4; ++nt) {
            int m = m0 + wm * 64 + mt * 16 + erow;
            int n = n0 + wn * 32 + nt * 8 + ecol;
            *(float2*)&P[(long)m * NCOL + n]       = make_float2(acc[mt][nt][0], acc[mt][nt][1]);
            *(float2*)&P[(long)(m + 8) * NCOL + n] = make_float2(acc[mt][nt][2], acc[mt][nt][3]);
        }
}

// ---------------- kernel D: reduce split-K partials + scatter ----------------
__global__ void k_reduce(float* __restrict__ out) {
    int t = blockIdx.x * blockDim.x + threadIdx.x;
    if (t >= OUT_ELEMS) return;
    float s = 0.f;
#pragma unroll
    for (int j = 0; j < NSPLIT; ++j)
        s += g_part[(long)j * OUT_ELEMS + t];
    int q = t >> 9, col = t & 511;
    int b = col >> 4, f = col & 15;
    out[(b * NQ + q) * NFILT + f] = s;   // out[b][q][f]
}

// ---------------- launch -----------------------------------------------------
extern "C" void kernel_launch(void* const* d_in, const int* in_sizes, int n_in,
                              void* d_out, int out_size) {
    const float *inputs = nullptr, *logits = nullptr, *filts = nullptr;
    for (int i = 0; i < n_in; ++i) {
        if (in_sizes[i] == BATCH * N_OBJ * N_OBJ * RDIM) inputs = (const float*)d_in[i];
        else if (in_sizes[i] == NQ * N_OBJ)              logits = (const float*)d_in[i];
        else if (in_sizes[i] == NFILT * 3 * 3 * RDIM)    filts = (const float*)d_in[i];
    }
    float* out = (float*)d_out;

    k_idx<<<20, 256>>>();
    k_pairconv<<<dim3(128, 3), 256>>>(inputs, filts);
    k_weights<<<NQ, 256>>>(logits);
    k_comb<<<1536, 256>>>();
    k_rcasm<<<dim3(20, 32), 256>>>();
    k_mma<<<dim3(4, 4, NSPLIT), 256>>>();
    k_reduce<<<(OUT_ELEMS + 511) / 512, 512>>>(out);
}

// round 11
// speedup vs baseline: 1.5806x; 1.0528x over previous
#include <cuda_runtime.h>
#include <cuda_bf16.h>
#include <cstdint>

#define N_OBJ 32
#define NFILT 16
#define RDIM 16
#define BATCH 32
#define NQ 512
#define NG 4960                  // C(32,3)
#define NCOL 512                 // BATCH * NFILT
#define OUT_ELEMS (NQ * NCOL)    // 262144
#define KP 14880                 // K' = 3*NG = 465 * 32 exactly
#define NSPLIT 15
#define ITERS 31                 // 465 / 15
#define BK 32
#define LDSW 40                  // smem row stride (halves); 80B rows, ldmatrix-safe
#define GCHUNK 248               // 4960 = 20 * 248

// ---------------- scratch (device globals) -----------------------------------
__device__ float         g_P  [BATCH * 9 * 1024 * 16];   // P[b][ac][i*32+j][f]
__device__ float         g_E  [3 * BATCH * 1024 * 16];   // E01,E02,E12 [e][b][xy][f]
__device__ __nv_bfloat16 g_Wb [NQ   * KP];               // A' [q][k']
__device__ __nv_bfloat16 g_RCb[NCOL * KP];               // B' [col][k']
__device__ float         g_part[NSPLIT * OUT_ELEMS];
__device__ int4          g_idx[NG];

// ---------------- helpers ----------------------------------------------------
__device__ __forceinline__ uint32_t smem_u32(const void* p) {
    uint32_t a;
    asm("{ .reg .u64 t; cvta.to.shared.u64 t, %1; cvt.u32.u64 %0, t; }" : "=r"(a) : "l"(p));
    return a;
}
__device__ __forceinline__ void ldmx4(uint32_t r[4], uint32_t addr) {
    asm volatile("ldmatrix.sync.aligned.m8n8.x4.shared.b16 {%0,%1,%2,%3}, [%4];"
                 : "=r"(r[0]), "=r"(r[1]), "=r"(r[2]), "=r"(r[3]) : "r"(addr));
}
__device__ __forceinline__ void mma_bf16(float c[4], const uint32_t a[4],
                                         uint32_t b0, uint32_t b1) {
    asm volatile("mma.sync.aligned.m16n8k16.row.col.f32.bf16.bf16.f32 "
                 "{%0,%1,%2,%3}, {%4,%5,%6,%7}, {%8,%9}, {%0,%1,%2,%3};"
                 : "+f"(c[0]), "+f"(c[1]), "+f"(c[2]), "+f"(c[3])
                 : "r"(a[0]), "r"(a[1]), "r"(a[2]), "r"(a[3]), "r"(b0), "r"(b1));
}
#define CP_ASYNC16(dst, src) \
    asm volatile("cp.async.cg.shared.global [%0], [%1], 16;" :: "r"(dst), "l"(src) : "memory")
#define CP_COMMIT() asm volatile("cp.async.commit_group;" ::: "memory")
#define CP_WAIT(n)  asm volatile("cp.async.wait_group %0;" :: "n"(n) : "memory")

// FMA-pipe exp: exp(x) for x <= 0 (softmax arg), ~1e-7 rel err, no MUFU.
__device__ __forceinline__ float fexp(float x) {
    x = fmaxf(x, -80.0f);
    float t = x * 1.4426950408889634f;          // x * log2(e)
    float tm = t + 12582912.0f;                 // 1.5 * 2^23 round-to-int trick
    int   n  = __float_as_int(tm) - 0x4B400000; // integer part
    float r  = t - (tm - 12582912.0f);          // r in [-0.5, 0.5]
    // 2^r = exp(r*ln2), degree-6 Taylor in u = r*ln2-free Horner on r
    float p = 1.540353039338161e-4f;
    p = p * r + 1.3333558146428443e-3f;
    p = p * r + 9.618129107628477e-3f;
    p = p * r + 5.550410866482158e-2f;
    p = p * r + 2.402265069591007e-1f;
    p = p * r + 6.931471805599453e-1f;
    p = p * r + 1.0f;
    return __int_as_float(__float_as_int(p) + (n << 23));
}

// ---------------- kernel 0: unrank C(32,3) -----------------------------------
__global__ void k_idx() {
    int g = blockIdx.x * blockDim.x + threadIdx.x;
    if (g >= NG) return;
    int r = g, i = 0;
    for (; i < 30; ++i) { int c = (31 - i) * (30 - i) / 2; if (r < c) break; r -= c; }
    int j = i + 1;
    for (; j < 31; ++j) { int c = 31 - j; if (r < c) break; r -= c; }
    g_idx[g] = make_int4(i, j, j + 1 + r, 0);
}

// ---------------- kernel P: pair conv  P[b][ac][ij][f] -----------------------
__global__ __launch_bounds__(256) void k_pairconv(const float* __restrict__ inputs,
                                                  const float* __restrict__ filters) {
    __shared__ float4 s_sf[3 * 16 * 4];      // [acl][d][f4]
    const int t = threadIdx.x;
    const int ac0 = blockIdx.y * 3;
#pragma unroll
    for (int u = 0; u < 3; ++u) {
        int idx = t + u * 256;               // < 768
        int acl = idx >> 8, r = idx & 255;
        int d = r >> 4, f = r & 15;
        ((float*)s_sf)[(acl * 16 + d) * 16 + f] =
            filters[(f * 9 + ac0 + acl) * 16 + d];
    }
    __syncthreads();

    const int cell = blockIdx.x * 256 + t;   // (b, ij) in [0, 32768)
    const float4* rv4 = (const float4*)(inputs + (long)cell * 16);
    float4 rv[4];
#pragma unroll
    for (int u = 0; u < 4; ++u) rv[u] = rv4[u];
    const float rs[16] = { rv[0].x, rv[0].y, rv[0].z, rv[0].w,
                           rv[1].x, rv[1].y, rv[1].z, rv[1].w,
                           rv[2].x, rv[2].y, rv[2].z, rv[2].w,
                           rv[3].x, rv[3].y, rv[3].z, rv[3].w };
    const int b = cell >> 10, ij = cell & 1023;

#pragma unroll
    for (int acl = 0; acl < 3; ++acl) {
        float4 acc[4] = { {0,0,0,0}, {0,0,0,0}, {0,0,0,0}, {0,0,0,0} };
#pragma unroll
        for (int d = 0; d < 16; ++d) {
            float xv = rs[d];
#pragma unroll
            for (int f4 = 0; f4 < 4; ++f4) {
                float4 sf = s_sf[(acl * 16 + d) * 4 + f4];
                acc[f4].x += xv * sf.x; acc[f4].y += xv * sf.y;
                acc[f4].z += xv * sf.z; acc[f4].w += xv * sf.w;
            }
        }
        float4* dst = (float4*)(g_P + ((long)(b * 9 + ac0 + acl) * 1024 + ij) * 16);
#pragma unroll
        for (int f4 = 0; f4 < 4; ++f4) dst[f4] = acc[f4];
    }
}

// ---------------- kernel E: combine planes (parallel over e,b,ij,f4) ---------
__global__ __launch_bounds__(256) void k_comb() {
    const int tid = blockIdx.x * 256 + threadIdx.x;   // < 393216
    const int f4 = tid & 3;
    const int cell = tid >> 2;                         // (e,b,ij)
    const int ij = cell & 1023;
    const int b = (cell >> 10) & 31;
    const int e = cell >> 15;
    const int x = ij >> 5, y = ij & 31;

    const int ns = (e == 0) ? 1 : (e == 1) ? 2 : 5;    // straight plane
    const int nt = (e == 0) ? 3 : (e == 1) ? 6 : 7;    // transposed plane
    const int nd = (e == 0) ? 0 : (e == 1) ? 8 : 4;    // diagonal plane
    const int dij = (e == 1) ? (y * 33) : (x * 33);
    const int ji = (y << 5) | x;

    const long pb = (long)b * 9 * 1024 * 4;            // float4 units per b-slab
    const float4* P = (const float4*)g_P;
    float4 a = P[pb + ((long)ns * 1024 + ij) * 4 + f4];
    float4 c = P[pb + ((long)nt * 1024 + ji) * 4 + f4];
    float4 d = P[pb + ((long)nd * 1024 + dij) * 4 + f4];
    ((float4*)g_E)[((long)(e * 32 + b) * 1024 + ij) * 4 + f4] =
        make_float4(a.x + c.x + d.x, a.y + c.y + d.y,
                    a.z + c.z + d.z, a.w + c.w + d.w);
}

// ---------------- kernel A: assemble rel_conv + split -> B' [col][k'] --------
__global__ __launch_bounds__(256) void k_rcasm() {
    __shared__ __nv_bfloat16 s_t[16][3 * GCHUNK];   // 16 rows x 744 bf16
    const int t = threadIdx.x;
    const int b = blockIdx.y, chunk = blockIdx.x;

    if (t < GCHUNK) {
        const int g = chunk * GCHUNK + t;
        const int4 id = g_idx[g];
        const float4* e01 = (const float4*)(g_E + ((long)(0 * 32 + b) * 1024 + id.x * 32 + id.y) * 16);
        const float4* e02 = (const float4*)(g_E + ((long)(1 * 32 + b) * 1024 + id.x * 32 + id.z) * 16);
        const float4* e12 = (const float4*)(g_E + ((long)(2 * 32 + b) * 1024 + id.y * 32 + id.z) * 16);
        float4 acc[4];
#pragma unroll
        for (int f4 = 0; f4 < 4; ++f4) {
            float4 a = e01[f4], c = e02[f4], d = e12[f4];
            acc[f4] = make_float4(a.x + c.x + d.x, a.y + c.y + d.y,
                                  a.z + c.z + d.z, a.w + c.w + d.w);
        }
        const float* af = (const float*)acc;
#pragma unroll
        for (int f = 0; f < 16; ++f) {
            float x = af[f];
            __nv_bfloat16 hi = __float2bfloat16(x);
            __nv_bfloat16 lo = __float2bfloat16(x - __bfloat162float(hi));
            s_t[f][3 * t]     = hi;
            s_t[f][3 * t + 1] = lo;
            s_t[f][3 * t + 2] = hi;
        }
    }
    __syncthreads();

#pragma unroll 1
    for (int r = 0; r < 16; ++r) {
        const uint32_t* src = (const uint32_t*)&s_t[r][0];
        uint32_t* dst = (uint32_t*)(g_RCb + (long)(b * 16 + r) * KP + chunk * (3 * GCHUNK));
        for (int idx = t; idx < (3 * GCHUNK) / 2; idx += 256) dst[idx] = src[idx];
    }
}

// ---------------- kernel B: weights -> A' triple [wh, wh, wl] ----------------
__global__ __launch_bounds__(256) void k_weights(const float* __restrict__ logits) {
    __shared__ float s_sp[N_OBJ];
    __shared__ float s_w[NG];
    __shared__ float s_red[8];
    const int q = blockIdx.x;
    const int t = threadIdx.x;

    if (t < N_OBJ) {
        float x = logits[q * N_OBJ + t];
        s_sp[t] = fmaxf(x, 0.f) + log1pf(expf(-fabsf(x)));
    }
    __syncthreads();

    float lmax = -1e30f;
    for (int g = t; g < NG; g += 256) {
        int4 id = g_idx[g];
        float w = s_sp[id.x] * s_sp[id.y] * s_sp[id.z];
        s_w[g] = w;
        lmax = fmaxf(lmax, w);
    }
#pragma unroll
    for (int o = 16; o; o >>= 1) lmax = fmaxf(lmax, __shfl_xor_sync(0xFFFFFFFFu, lmax, o));
    if ((t & 31) == 0) s_red[t >> 5] = lmax;
    __syncthreads();
    float bmax = s_red[0];
#pragma unroll
    for (int w = 1; w < 8; ++w) bmax = fmaxf(bmax, s_red[w]);
    __syncthreads();

    float lsum = 0.f;
    for (int g = t; g < NG; g += 256) {
        float e = fexp(s_w[g] - bmax);          // FMA-pipe exp (no MUFU)
        s_w[g] = e;
        lsum += e;
    }
#pragma unroll
    for (int o = 16; o; o >>= 1) lsum += __shfl_xor_sync(0xFFFFFFFFu, lsum, o);
    if ((t & 31) == 0) s_red[t >> 5] = lsum;
    __syncthreads();
    float bsum = 0.f;
#pragma unroll
    for (int w = 0; w < 8; ++w) bsum += s_red[w];
    float inv = 1.0f / bsum;

    for (int g = t; g < NG; g += 256) {
        float w = s_w[g] * inv;
        __nv_bfloat16 hi = __float2bfloat16(w);
        __nv_bfloat16 lo = __float2bfloat16(w - __bfloat162float(hi));
        __nv_bfloat16* dst = g_Wb + (long)q * KP + 3 * g;
        dst[0] = hi; dst[1] = hi; dst[2] = lo;
    }
}

// ---------------- kernel C: bf16 HMMA GEMM, cp.async double-buffered ---------
// 512x512xKP, split-K=15 (31 iters, 240 CTAs = one full wave @2/SM).
__global__ __launch_bounds__(256, 2) void k_mma() {
    __shared__ __align__(16) __nv_bfloat16 sA[2][128 * LDSW];
    __shared__ __align__(16) __nv_bfloat16 sB[2][128 * LDSW];
    const int t = threadIdx.x, lane = t & 31, wid = t >> 5;
    const int wm = wid & 1, wn = wid >> 1;
    const int m0 = blockIdx.y * 128, n0 = blockIdx.x * 128;
    const long kbase = (long)blockIdx.z * ITERS * BK;

    float acc[4][4][4];
#pragma unroll
    for (int i = 0; i < 4; ++i)
#pragma unroll
        for (int j = 0; j < 4; ++j)
#pragma unroll
            for (int v = 0; v < 4; ++v) acc[i][j][v] = 0.f;

    const int grow = t >> 2, gq = t & 3;
    const uint32_t sA0 = smem_u32(sA), sB0 = smem_u32(sB);
    const uint32_t BUFB = 128 * LDSW * 2;
    const uint32_t dA0 = sA0 + (uint32_t)((grow * LDSW + gq * 8) * 2);
    const uint32_t dA1 = dA0 + (uint32_t)(64 * LDSW * 2);
    const uint32_t dB0 = sB0 + (uint32_t)((grow * LDSW + gq * 8) * 2);
    const uint32_t dB1 = dB0 + (uint32_t)(64 * LDSW * 2);

    const int lr = lane & 15, lh = lane >> 4;
    const uint32_t aBase = sA0 + (uint32_t)(((wm * 64 + lr) * LDSW + lh * 8) * 2);
    const uint32_t bBase = sB0 + (uint32_t)(((wn * 32 + lr) * LDSW + lh * 8) * 2);

    {
        const long k0 = kbase;
        CP_ASYNC16(dA0, g_Wb  + (long)(m0 + grow)      * KP + k0 + gq * 8);
        CP_ASYNC16(dA1, g_Wb  + (long)(m0 + grow + 64) * KP + k0 + gq * 8);
        CP_ASYNC16(dB0, g_RCb + (long)(n0 + grow)      * KP + k0 + gq * 8);
        CP_ASYNC16(dB1, g_RCb + (long)(n0 + grow + 64) * KP + k0 + gq * 8);
        CP_COMMIT();
    }

#pragma unroll 1
    for (int tt = 0; tt < ITERS; ++tt) {
        if (tt + 1 < ITERS) {
            const long k0 = kbase + (long)(tt + 1) * BK;
            const uint32_t bo = ((tt + 1) & 1) * BUFB;
            CP_ASYNC16(dA0 + bo, g_Wb  + (long)(m0 + grow)      * KP + k0 + gq * 8);
            CP_ASYNC16(dA1 + bo, g_Wb  + (long)(m0 + grow + 64) * KP + k0 + gq * 8);
            CP_ASYNC16(dB0 + bo, g_RCb + (long)(n0 + grow)      * KP + k0 + gq * 8);
            CP_ASYNC16(dB1 + bo, g_RCb + (long)(n0 + grow + 64) * KP + k0 + gq * 8);
            CP_COMMIT();
            CP_WAIT(1);
        } else {
            CP_WAIT(0);
        }
        __syncthreads();

        const uint32_t bo = (tt & 1) * BUFB;
#pragma unroll
        for (int ks = 0; ks < 2; ++ks) {
            uint32_t af[4][4], bf[2][4];
#pragma unroll
            for (int mt = 0; mt < 4; ++mt)
                ldmx4(af[mt], aBase + bo + mt * (16 * LDSW * 2) + ks * 32);
#pragma unroll
            for (int np = 0; np < 2; ++np)
                ldmx4(bf[np], bBase + bo + np * (16 * LDSW * 2) + ks * 32);
#pragma unroll
            for (int mt = 0; mt < 4; ++mt)
#pragma unroll
                for (int nt = 0; nt < 4; ++nt)
                    mma_bf16(acc[mt][nt], af[mt], bf[nt >> 1][nt & 1],
                             bf[nt >> 1][(nt & 1) + 2]);
        }
        __syncthreads();
    }

    float* P = g_part + (long)blockIdx.z * OUT_ELEMS;
    const int erow = lane >> 2, ecol = (lane & 3) * 2;
#pragma unroll
    for (int mt = 0; mt < 4; ++mt)
#pragma unroll
        for (int nt = 0; nt < 4; ++nt) {
            int m = m0 + wm * 64 + mt * 16 + erow;
            int n = n0 + wn * 32 + nt * 8 + ecol;
            *(float2*)&P[(long)m * NCOL + n]       = make_float2(acc[mt][nt][0], acc[mt][nt][1]);
            *(float2*)&P[(long)(m + 8) * NCOL + n] = make_float2(acc[mt][nt][2], acc[mt][nt][3]);
        }
}

// ---------------- kernel D: reduce split-K partials + scatter ----------------
__global__ void k_reduce(float* __restrict__ out) {
    int t = blockIdx.x * blockDim.x + threadIdx.x;
    if (t >= OUT_ELEMS) return;
    float s = 0.f;
#pragma unroll
    for (int j = 0; j < NSPLIT; ++j)
        s += g_part[(long)j * OUT_ELEMS + t];
    int q = t >> 9, col = t & 511;
    int b = col >> 4, f = col & 15;
    out[(b * NQ + q) * NFILT + f] = s;   // out[b][q][f]
}

// ---------------- launch -----------------------------------------------------
extern "C" void kernel_launch(void* const* d_in, const int* in_sizes, int n_in,
                              void* d_out, int out_size) {
    const float *inputs = nullptr, *logits = nullptr, *filts = nullptr;
    for (int i = 0; i < n_in; ++i) {
        if (in_sizes[i] == BATCH * N_OBJ * N_OBJ * RDIM) inputs = (const float*)d_in[i];
        else if (in_sizes[i] == NQ * N_OBJ)              logits = (const float*)d_in[i];
        else if (in_sizes[i] == NFILT * 3 * 3 * RDIM)    filts = (const float*)d_in[i];
    }
    float* out = (float*)d_out;

    k_idx<<<20, 256>>>();
    k_pairconv<<<dim3(128, 3), 256>>>(inputs, filts);
    k_weights<<<NQ, 256>>>(logits);
    k_comb<<<1536, 256>>>();
    k_rcasm<<<dim3(20, 32), 256>>>();
    k_mma<<<dim3(4, 4, NSPLIT), 256>>>();
    k_reduce<<<(OUT_ELEMS + 511) / 512, 512>>>(out);
}

// round 12
// speedup vs baseline: 2.2981x; 1.4540x over previous
#include <cuda_runtime.h>
#include <cuda_bf16.h>
#include <cuda_fp16.h>
#include <cstdint>

#define N_OBJ 32
#define NFILT 16
#define RDIM 16
#define BATCH 32
#define NQ 512
#define NG 4960                  // C(32,3)
#define NCOL 512                 // BATCH * NFILT
#define OUT_ELEMS (NQ * NCOL)    // 262144
#define KP 4960                  // K = NG, = 155 * 32 exactly
#define NSPLIT 31
#define ITERS 5                  // 155 / 31
#define BK 32
#define LDSW 40                  // smem row stride (halves); 80B rows, ldmatrix-safe
#define GCHUNK 248               // 4960 = 20 * 248

// ---------------- scratch (device globals) -----------------------------------
__device__ float  g_P  [BATCH * 9 * 1024 * 16];   // P[b][ac][i*32+j][f]
__device__ float  g_E  [3 * BATCH * 1024 * 16];   // E01,E02,E12 [e][b][xy][f]
__device__ __half g_Wb [NQ   * KP];               // A [q][k]   fp16
__device__ __half g_RCb[NCOL * KP];               // B [col][k] fp16
__device__ float  g_part[NSPLIT * OUT_ELEMS];
__device__ int4   g_idx[NG];

// ---------------- helpers ----------------------------------------------------
__device__ __forceinline__ uint32_t smem_u32(const void* p) {
    uint32_t a;
    asm("{ .reg .u64 t; cvta.to.shared.u64 t, %1; cvt.u32.u64 %0, t; }" : "=r"(a) : "l"(p));
    return a;
}
__device__ __forceinline__ void ldmx4(uint32_t r[4], uint32_t addr) {
    asm volatile("ldmatrix.sync.aligned.m8n8.x4.shared.b16 {%0,%1,%2,%3}, [%4];"
                 : "=r"(r[0]), "=r"(r[1]), "=r"(r[2]), "=r"(r[3]) : "r"(addr));
}
__device__ __forceinline__ void mma_f16(float c[4], const uint32_t a[4],
                                        uint32_t b0, uint32_t b1) {
    asm volatile("mma.sync.aligned.m16n8k16.row.col.f32.f16.f16.f32 "
                 "{%0,%1,%2,%3}, {%4,%5,%6,%7}, {%8,%9}, {%0,%1,%2,%3};"
                 : "+f"(c[0]), "+f"(c[1]), "+f"(c[2]), "+f"(c[3])
                 : "r"(a[0]), "r"(a[1]), "r"(a[2]), "r"(a[3]), "r"(b0), "r"(b1));
}
#define CP_ASYNC16(dst, src) \
    asm volatile("cp.async.cg.shared.global [%0], [%1], 16;" :: "r"(dst), "l"(src) : "memory")
#define CP_COMMIT() asm volatile("cp.async.commit_group;" ::: "memory")
#define CP_WAIT(n)  asm volatile("cp.async.wait_group %0;" :: "n"(n) : "memory")

// FMA-pipe exp: exp(x) for x <= 0 (softmax arg), ~1e-7 rel err, no MUFU.
__device__ __forceinline__ float fexp(float x) {
    x = fmaxf(x, -80.0f);
    float t = x * 1.4426950408889634f;
    float tm = t + 12582912.0f;
    int   n  = __float_as_int(tm) - 0x4B400000;
    float r  = t - (tm - 12582912.0f);
    float p = 1.540353039338161e-4f;
    p = p * r + 1.3333558146428443e-3f;
    p = p * r + 9.618129107628477e-3f;
    p = p * r + 5.550410866482158e-2f;
    p = p * r + 2.402265069591007e-1f;
    p = p * r + 6.931471805599453e-1f;
    p = p * r + 1.0f;
    return __int_as_float(__float_as_int(p) + (n << 23));
}

// ---------------- kernel 0: unrank C(32,3) -----------------------------------
__global__ void k_idx() {
    int g = blockIdx.x * blockDim.x + threadIdx.x;
    if (g >= NG) return;
    int r = g, i = 0;
    for (; i < 30; ++i) { int c = (31 - i) * (30 - i) / 2; if (r < c) break; r -= c; }
    int j = i + 1;
    for (; j < 31; ++j) { int c = 31 - j; if (r < c) break; r -= c; }
    g_idx[g] = make_int4(i, j, j + 1 + r, 0);
}

// ---------------- kernel P: pair conv  P[b][ac][ij][f] -----------------------
__global__ __launch_bounds__(256) void k_pairconv(const float* __restrict__ inputs,
                                                  const float* __restrict__ filters) {
    __shared__ float4 s_sf[3 * 16 * 4];
    const int t = threadIdx.x;
    const int ac0 = blockIdx.y * 3;
#pragma unroll
    for (int u = 0; u < 3; ++u) {
        int idx = t + u * 256;
        int acl = idx >> 8, r = idx & 255;
        int d = r >> 4, f = r & 15;
        ((float*)s_sf)[(acl * 16 + d) * 16 + f] =
            filters[(f * 9 + ac0 + acl) * 16 + d];
    }
    __syncthreads();

    const int cell = blockIdx.x * 256 + t;
    const float4* rv4 = (const float4*)(inputs + (long)cell * 16);
    float4 rv[4];
#pragma unroll
    for (int u = 0; u < 4; ++u) rv[u] = rv4[u];
    const float rs[16] = { rv[0].x, rv[0].y, rv[0].z, rv[0].w,
                           rv[1].x, rv[1].y, rv[1].z, rv[1].w,
                           rv[2].x, rv[2].y, rv[2].z, rv[2].w,
                           rv[3].x, rv[3].y, rv[3].z, rv[3].w };
    const int b = cell >> 10, ij = cell & 1023;

#pragma unroll
    for (int acl = 0; acl < 3; ++acl) {
        float4 acc[4] = { {0,0,0,0}, {0,0,0,0}, {0,0,0,0}, {0,0,0,0} };
#pragma unroll
        for (int d = 0; d < 16; ++d) {
            float xv = rs[d];
#pragma unroll
            for (int f4 = 0; f4 < 4; ++f4) {
                float4 sf = s_sf[(acl * 16 + d) * 4 + f4];
                acc[f4].x += xv * sf.x; acc[f4].y += xv * sf.y;
                acc[f4].z += xv * sf.z; acc[f4].w += xv * sf.w;
            }
        }
        float4* dst = (float4*)(g_P + ((long)(b * 9 + ac0 + acl) * 1024 + ij) * 16);
#pragma unroll
        for (int f4 = 0; f4 < 4; ++f4) dst[f4] = acc[f4];
    }
}

// ---------------- kernel E: combine planes (parallel over e,b,ij,f4) ---------
__global__ __launch_bounds__(256) void k_comb() {
    const int tid = blockIdx.x * 256 + threadIdx.x;
    const int f4 = tid & 3;
    const int cell = tid >> 2;
    const int ij = cell & 1023;
    const int b = (cell >> 10) & 31;
    const int e = cell >> 15;
    const int x = ij >> 5, y = ij & 31;

    const int ns = (e == 0) ? 1 : (e == 1) ? 2 : 5;
    const int nt = (e == 0) ? 3 : (e == 1) ? 6 : 7;
    const int nd = (e == 0) ? 0 : (e == 1) ? 8 : 4;
    const int dij = (e == 1) ? (y * 33) : (x * 33);
    const int ji = (y << 5) | x;

    const long pb = (long)b * 9 * 1024 * 4;
    const float4* P = (const float4*)g_P;
    float4 a = P[pb + ((long)ns * 1024 + ij) * 4 + f4];
    float4 c = P[pb + ((long)nt * 1024 + ji) * 4 + f4];
    float4 d = P[pb + ((long)nd * 1024 + dij) * 4 + f4];
    ((float4*)g_E)[((long)(e * 32 + b) * 1024 + ij) * 4 + f4] =
        make_float4(a.x + c.x + d.x, a.y + c.y + d.y,
                    a.z + c.z + d.z, a.w + c.w + d.w);
}

// ---------------- kernel A: assemble rel_conv -> B [col][k] fp16 -------------
__global__ __launch_bounds__(256) void k_rcasm() {
    __shared__ __half s_t[16][GCHUNK];   // 16 rows x 248 fp16
    const int t = threadIdx.x;
    const int b = blockIdx.y, chunk = blockIdx.x;

    if (t < GCHUNK) {
        const int g = chunk * GCHUNK + t;
        const int4 id = g_idx[g];
        const float4* e01 = (const float4*)(g_E + ((long)(0 * 32 + b) * 1024 + id.x * 32 + id.y) * 16);
        const float4* e02 = (const float4*)(g_E + ((long)(1 * 32 + b) * 1024 + id.x * 32 + id.z) * 16);
        const float4* e12 = (const float4*)(g_E + ((long)(2 * 32 + b) * 1024 + id.y * 32 + id.z) * 16);
        float4 acc[4];
#pragma unroll
        for (int f4 = 0; f4 < 4; ++f4) {
            float4 a = e01[f4], c = e02[f4], d = e12[f4];
            acc[f4] = make_float4(a.x + c.x + d.x, a.y + c.y + d.y,
                                  a.z + c.z + d.z, a.w + c.w + d.w);
        }
        const float* af = (const float*)acc;
#pragma unroll
        for (int f = 0; f < 16; ++f)
            s_t[f][t] = __float2half(af[f]);
    }
    __syncthreads();

    // coalesced copy out: 16 rows x 248 fp16 = 124 u32 each
#pragma unroll 1
    for (int r = 0; r < 16; ++r) {
        const uint32_t* src = (const uint32_t*)&s_t[r][0];
        uint32_t* dst = (uint32_t*)(g_RCb + (long)(b * 16 + r) * KP + chunk * GCHUNK);
        for (int idx = t; idx < GCHUNK / 2; idx += 256) dst[idx] = src[idx];
    }
}

// ---------------- kernel B: weights -> A [q][k] fp16 -------------------------
__global__ __launch_bounds__(256) void k_weights(const float* __restrict__ logits) {
    __shared__ float s_sp[N_OBJ];
    __shared__ float s_w[NG];
    __shared__ float s_red[8];
    const int q = blockIdx.x;
    const int t = threadIdx.x;

    if (t < N_OBJ) {
        float x = logits[q * N_OBJ + t];
        s_sp[t] = fmaxf(x, 0.f) + log1pf(expf(-fabsf(x)));
    }
    __syncthreads();

    float lmax = -1e30f;
    for (int g = t; g < NG; g += 256) {
        int4 id = g_idx[g];
        float w = s_sp[id.x] * s_sp[id.y] * s_sp[id.z];
        s_w[g] = w;
        lmax = fmaxf(lmax, w);
    }
#pragma unroll
    for (int o = 16; o; o >>= 1) lmax = fmaxf(lmax, __shfl_xor_sync(0xFFFFFFFFu, lmax, o));
    if ((t & 31) == 0) s_red[t >> 5] = lmax;
    __syncthreads();
    float bmax = s_red[0];
#pragma unroll
    for (int w = 1; w < 8; ++w) bmax = fmaxf(bmax, s_red[w]);
    __syncthreads();

    float lsum = 0.f;
    for (int g = t; g < NG; g += 256) {
        float e = fexp(s_w[g] - bmax);
        s_w[g] = e;
        lsum += e;
    }
#pragma unroll
    for (int o = 16; o; o >>= 1) lsum += __shfl_xor_sync(0xFFFFFFFFu, lsum, o);
    if ((t & 31) == 0) s_red[t >> 5] = lsum;
    __syncthreads();
    float bsum = 0.f;
#pragma unroll
    for (int w = 0; w < 8; ++w) bsum += s_red[w];
    float inv = 1.0f / bsum;
    __syncthreads();

    // packed coalesced fp16 store, 2 g per u32
    uint32_t* dst = (uint32_t*)(g_Wb + (long)q * KP);
    for (int g2 = t; g2 < NG / 2; g2 += 256) {
        __half2 h = __floats2half2_rn(s_w[2 * g2] * inv, s_w[2 * g2 + 1] * inv);
        dst[g2] = *(const uint32_t*)&h;
    }
}

// ---------------- kernel C: fp16 HMMA GEMM 512x512x4960, split-K=31 ----------
// BM=BN=128, BK=32, 8 warps 2(m)x4(n), cp.async double-buffered, 5 iters/CTA.
__global__ __launch_bounds__(256, 2) void k_mma() {
    __shared__ __align__(16) __half sA[2][128 * LDSW];
    __shared__ __align__(16) __half sB[2][128 * LDSW];
    const int t = threadIdx.x, lane = t & 31, wid = t >> 5;
    const int wm = wid & 1, wn = wid >> 1;
    const int m0 = blockIdx.y * 128, n0 = blockIdx.x * 128;
    const long kbase = (long)blockIdx.z * ITERS * BK;

    float acc[4][4][4];
#pragma unroll
    for (int i = 0; i < 4; ++i)
#pragma unroll
        for (int j = 0; j < 4; ++j)
#pragma unroll
            for (int v = 0; v < 4; ++v) acc[i][j][v] = 0.f;

    const int grow = t >> 2, gq = t & 3;
    const uint32_t sA0 = smem_u32(sA), sB0 = smem_u32(sB);
    const uint32_t BUFB = 128 * LDSW * 2;
    const uint32_t dA0 = sA0 + (uint32_t)((grow * LDSW + gq * 8) * 2);
    const uint32_t dA1 = dA0 + (uint32_t)(64 * LDSW * 2);
    const uint32_t dB0 = sB0 + (uint32_t)((grow * LDSW + gq * 8) * 2);
    const uint32_t dB1 = dB0 + (uint32_t)(64 * LDSW * 2);

    const int lr = lane & 15, lh = lane >> 4;
    const uint32_t aBase = sA0 + (uint32_t)(((wm * 64 + lr) * LDSW + lh * 8) * 2);
    const uint32_t bBase = sB0 + (uint32_t)(((wn * 32 + lr) * LDSW + lh * 8) * 2);

    {
        const long k0 = kbase;
        CP_ASYNC16(dA0, g_Wb  + (long)(m0 + grow)      * KP + k0 + gq * 8);
        CP_ASYNC16(dA1, g_Wb  + (long)(m0 + grow + 64) * KP + k0 + gq * 8);
        CP_ASYNC16(dB0, g_RCb + (long)(n0 + grow)      * KP + k0 + gq * 8);
        CP_ASYNC16(dB1, g_RCb + (long)(n0 + grow + 64) * KP + k0 + gq * 8);
        CP_COMMIT();
    }

#pragma unroll 1
    for (int tt = 0; tt < ITERS; ++tt) {
        if (tt + 1 < ITERS) {
            const long k0 = kbase + (long)(tt + 1) * BK;
            const uint32_t bo = ((tt + 1) & 1) * BUFB;
            CP_ASYNC16(dA0 + bo, g_Wb  + (long)(m0 + grow)      * KP + k0 + gq * 8);
            CP_ASYNC16(dA1 + bo, g_Wb  + (long)(m0 + grow + 64) * KP + k0 + gq * 8);
            CP_ASYNC16(dB0 + bo, g_RCb + (long)(n0 + grow)      * KP + k0 + gq * 8);
            CP_ASYNC16(dB1 + bo, g_RCb + (long)(n0 + grow + 64) * KP + k0 + gq * 8);
            CP_COMMIT();
            CP_WAIT(1);
        } else {
            CP_WAIT(0);
        }
        __syncthreads();

        const uint32_t bo = (tt & 1) * BUFB;
#pragma unroll
        for (int ks = 0; ks < 2; ++ks) {
            uint32_t af[4][4], bf[2][4];
#pragma unroll
            for (int mt = 0; mt < 4; ++mt)
                ldmx4(af[mt], aBase + bo + mt * (16 * LDSW * 2) + ks * 32);
#pragma unroll
            for (int np = 0; np < 2; ++np)
                ldmx4(bf[np], bBase + bo + np * (16 * LDSW * 2) + ks * 32);
#pragma unroll
            for (int mt = 0; mt < 4; ++mt)
#pragma unroll
                for (int nt = 0; nt < 4; ++nt)
                    mma_f16(acc[mt][nt], af[mt], bf[nt >> 1][nt & 1],
                            bf[nt >> 1][(nt & 1) + 2]);
        }
        __syncthreads();
    }

    float* P = g_part + (long)blockIdx.z * OUT_ELEMS;
    const int erow = lane >> 2, ecol = (lane & 3) * 2;
#pragma unroll
    for (int mt = 0; mt < 4; ++mt)
#pragma unroll
        for (int nt = 0; nt < 4; ++nt) {
            int m = m0 + wm * 64 + mt * 16 + erow;
            int n = n0 + wn * 32 + nt * 8 + ecol;
            *(float2*)&P[(long)m * NCOL + n]       = make_float2(acc[mt][nt][0], acc[mt][nt][1]);
            *(float2*)&P[(long)(m + 8) * NCOL + n] = make_float2(acc[mt][nt][2], acc[mt][nt][3]);
        }
}

// ---------------- kernel D: reduce split-K partials + scatter ----------------
__global__ void k_reduce(float* __restrict__ out) {
    int t = blockIdx.x * blockDim.x + threadIdx.x;
    if (t >= OUT_ELEMS) return;
    float s = 0.f;
#pragma unroll
    for (int j = 0; j < NSPLIT; ++j)
        s += g_part[(long)j * OUT_ELEMS + t];
    int q = t >> 9, col = t & 511;
    int b = col >> 4, f = col & 15;
    out[(b * NQ + q) * NFILT + f] = s;   // out[b][q][f]
}

// ---------------- launch -----------------------------------------------------
extern "C" void kernel_launch(void* const* d_in, const int* in_sizes, int n_in,
                              void* d_out, int out_size) {
    const float *inputs = nullptr, *logits = nullptr, *filts = nullptr;
    for (int i = 0; i < n_in; ++i) {
        if (in_sizes[i] == BATCH * N_OBJ * N_OBJ * RDIM) inputs = (const float*)d_in[i];
        else if (in_sizes[i] == NQ * N_OBJ)              logits = (const float*)d_in[i];
        else if (in_sizes[i] == NFILT * 3 * 3 * RDIM)    filts = (const float*)d_in[i];
    }
    float* out = (float*)d_out;

    k_idx<<<20, 256>>>();
    k_pairconv<<<dim3(128, 3), 256>>>(inputs, filts);
    k_weights<<<NQ, 256>>>(logits);
    k_comb<<<1536, 256>>>();
    k_rcasm<<<dim3(20, 32), 256>>>();
    k_mma<<<dim3(4, 4, NSPLIT), 256>>>();
    k_reduce<<<(OUT_ELEMS + 511) / 512, 512>>>(out);
}

// round 13
// speedup vs baseline: 2.5123x; 1.0932x over previous
#include <cuda_runtime.h>
#include <cuda_bf16.h>
#include <cuda_fp16.h>
#include <cstdint>

#define N_OBJ 32
#define NFILT 16
#define RDIM 16
#define BATCH 32
#define NQ 512
#define NG 4960                  // C(32,3)
#define NCOL 512                 // BATCH * NFILT
#define OUT_ELEMS (NQ * NCOL)    // 262144
#define KP 4960                  // K = NG, = 155 * 32 exactly
#define NSPLIT 31
#define ITERS 5                  // 155 / 31
#define BK 32
#define LDSW 40                  // smem row stride (halves); 80B rows, ldmatrix-safe
#define GCHUNK 248               // 4960 = 20 * 248

// ---------------- scratch (device globals) -----------------------------------
__device__ float  g_E  [3 * BATCH * 1024 * 16];   // E01,E02,E12 [e][b][xy][f]
__device__ __half g_Wb [NQ   * KP];               // A [q][k]   fp16
__device__ __half g_RCb[NCOL * KP];               // B [col][k] fp16
__device__ __half g_part[NSPLIT * OUT_ELEMS];     // fp16 split-K partials
__device__ uchar4 g_idx[NG];                      // packed combination table

// ---------------- helpers ----------------------------------------------------
__device__ __forceinline__ uint32_t smem_u32(const void* p) {
    uint32_t a;
    asm("{ .reg .u64 t; cvta.to.shared.u64 t, %1; cvt.u32.u64 %0, t; }" : "=r"(a) : "l"(p));
    return a;
}
__device__ __forceinline__ void ldmx4(uint32_t r[4], uint32_t addr) {
    asm volatile("ldmatrix.sync.aligned.m8n8.x4.shared.b16 {%0,%1,%2,%3}, [%4];"
                 : "=r"(r[0]), "=r"(r[1]), "=r"(r[2]), "=r"(r[3]) : "r"(addr));
}
__device__ __forceinline__ void mma_f16(float c[4], const uint32_t a[4],
                                        uint32_t b0, uint32_t b1) {
    asm volatile("mma.sync.aligned.m16n8k16.row.col.f32.f16.f16.f32 "
                 "{%0,%1,%2,%3}, {%4,%5,%6,%7}, {%8,%9}, {%0,%1,%2,%3};"
                 : "+f"(c[0]), "+f"(c[1]), "+f"(c[2]), "+f"(c[3])
                 : "r"(a[0]), "r"(a[1]), "r"(a[2]), "r"(a[3]), "r"(b0), "r"(b1));
}
#define CP_ASYNC16(dst, src) \
    asm volatile("cp.async.cg.shared.global [%0], [%1], 16;" :: "r"(dst), "l"(src) : "memory")
#define CP_COMMIT() asm volatile("cp.async.commit_group;" ::: "memory")
#define CP_WAIT(n)  asm volatile("cp.async.wait_group %0;" :: "n"(n) : "memory")

// FMA-pipe exp: exp(x) for x <= 0 (softmax arg), ~1e-7 rel err, no MUFU.
__device__ __forceinline__ float fexp(float x) {
    x = fmaxf(x, -80.0f);
    float t = x * 1.4426950408889634f;
    float tm = t + 12582912.0f;
    int   n  = __float_as_int(tm) - 0x4B400000;
    float r  = t - (tm - 12582912.0f);
    float p = 1.540353039338161e-4f;
    p = p * r + 1.3333558146428443e-3f;
    p = p * r + 9.618129107628477e-3f;
    p = p * r + 5.550410866482158e-2f;
    p = p * r + 2.402265069591007e-1f;
    p = p * r + 6.931471805599453e-1f;
    p = p * r + 1.0f;
    return __int_as_float(__float_as_int(p) + (n << 23));
}

// ---------------- kernel 0: unrank C(32,3) -> uchar4 -------------------------
__global__ void k_idx() {
    int g = blockIdx.x * blockDim.x + threadIdx.x;
    if (g >= NG) return;
    int r = g, i = 0;
    for (; i < 30; ++i) { int c = (31 - i) * (30 - i) / 2; if (r < c) break; r -= c; }
    int j = i + 1;
    for (; j < 31; ++j) { int c = 31 - j; if (r < c) break; r -= c; }
    g_idx[g] = make_uchar4((unsigned char)i, (unsigned char)j,
                           (unsigned char)(j + 1 + r), 0);
}

// ---------------- kernel F: fused pairconv + plane combine -> E --------------
// Per thread (b, x, y): E01 = in[x,y]·F1 + in[y,x]·F3 + in[x,x]·F0
//                       E02 = in[x,y]·F2 + in[y,x]·F6 + in[y,y]·F8
//                       E12 = in[x,y]·F5 + in[y,x]·F7 + in[x,x]·F4
__global__ __launch_bounds__(256) void k_fused(const float* __restrict__ inputs,
                                               const float* __restrict__ filters) {
    __shared__ float4 s_f[9 * 16 * 4];          // [ac][d][f4]
    const int t = threadIdx.x;
#pragma unroll
    for (int u = 0; u < 9; ++u) {
        int idx = t + u * 256;                  // < 2304
        int ac = idx >> 8, rem = idx & 255;
        int d = rem >> 4, f = rem & 15;
        ((float*)s_f)[((ac * 16 + d) << 4) + f] = filters[(f * 9 + ac) * 16 + d];
    }
    __syncthreads();

    const int cell = blockIdx.x * 256 + t;      // (b, xy) in [0, 32768)
    const int b = cell >> 10, ij = cell & 1023;
    const int x = ij >> 5, y = ij & 31;
    const float4* base = (const float4*)(inputs + (long)b * 16384);

    float4 rij[4], rji[4], rxx[4], ryy[4];
#pragma unroll
    for (int u = 0; u < 4; ++u) {
        rij[u] = base[(x * 32 + y) * 4 + u];
        rji[u] = base[(y * 32 + x) * 4 + u];
        rxx[u] = base[(x * 33) * 4 + u];
        ryy[u] = base[(y * 33) * 4 + u];
    }
    const float* fij = (const float*)rij;
    const float* fji = (const float*)rji;
    const float* fxx = (const float*)rxx;
    const float* fyy = (const float*)ryy;

#pragma unroll
    for (int e = 0; e < 3; ++e) {
        const int ps = (e == 0) ? 1 : (e == 1) ? 2 : 5;
        const int pt = (e == 0) ? 3 : (e == 1) ? 6 : 7;
        const int pd = (e == 0) ? 0 : (e == 1) ? 8 : 4;
        const float* fd = (e == 1) ? fyy : fxx;
        float4 acc[4] = { {0,0,0,0}, {0,0,0,0}, {0,0,0,0}, {0,0,0,0} };
#pragma unroll
        for (int d = 0; d < 16; ++d) {
            float a = fij[d], bb = fji[d], c = fd[d];
#pragma unroll
            for (int f4 = 0; f4 < 4; ++f4) {
                float4 v1 = s_f[(ps * 16 + d) * 4 + f4];
                float4 v2 = s_f[(pt * 16 + d) * 4 + f4];
                float4 v3 = s_f[(pd * 16 + d) * 4 + f4];
                acc[f4].x += a * v1.x + bb * v2.x + c * v3.x;
                acc[f4].y += a * v1.y + bb * v2.y + c * v3.y;
                acc[f4].z += a * v1.z + bb * v2.z + c * v3.z;
                acc[f4].w += a * v1.w + bb * v2.w + c * v3.w;
            }
        }
        float4* dst = (float4*)(g_E + ((long)(e * 32 + b) * 1024 + ij) * 16);
#pragma unroll
        for (int f4 = 0; f4 < 4; ++f4) dst[f4] = acc[f4];
    }
}

// ---------------- kernel A: assemble rel_conv -> B [col][k] fp16 -------------
__global__ __launch_bounds__(256) void k_rcasm() {
    __shared__ __half s_t[16][GCHUNK];   // 16 rows x 248 fp16
    const int t = threadIdx.x;
    const int b = blockIdx.y, chunk = blockIdx.x;

    if (t < GCHUNK) {
        const int g = chunk * GCHUNK + t;
        const uchar4 id = g_idx[g];
        const float4* e01 = (const float4*)(g_E + ((long)(0 * 32 + b) * 1024 + id.x * 32 + id.y) * 16);
        const float4* e02 = (const float4*)(g_E + ((long)(1 * 32 + b) * 1024 + id.x * 32 + id.z) * 16);
        const float4* e12 = (const float4*)(g_E + ((long)(2 * 32 + b) * 1024 + id.y * 32 + id.z) * 16);
        float4 acc[4];
#pragma unroll
        for (int f4 = 0; f4 < 4; ++f4) {
            float4 a = e01[f4], c = e02[f4], d = e12[f4];
            acc[f4] = make_float4(a.x + c.x + d.x, a.y + c.y + d.y,
                                  a.z + c.z + d.z, a.w + c.w + d.w);
        }
        const float* af = (const float*)acc;
#pragma unroll
        for (int f = 0; f < 16; ++f)
            s_t[f][t] = __float2half(af[f]);
    }
    __syncthreads();

#pragma unroll 1
    for (int r = 0; r < 16; ++r) {
        const uint32_t* src = (const uint32_t*)&s_t[r][0];
        uint32_t* dst = (uint32_t*)(g_RCb + (long)(b * 16 + r) * KP + chunk * GCHUNK);
        for (int idx = t; idx < GCHUNK / 2; idx += 256) dst[idx] = src[idx];
    }
}

// ---------------- kernel B: weights -> A [q][k] fp16 -------------------------
__global__ __launch_bounds__(256) void k_weights(const float* __restrict__ logits) {
    __shared__ float s_sp[N_OBJ];
    __shared__ float s_w[NG];
    __shared__ float s_red[8];
    const int q = blockIdx.x;
    const int t = threadIdx.x;

    if (t < N_OBJ) {
        float x = logits[q * N_OBJ + t];
        s_sp[t] = fmaxf(x, 0.f) + log1pf(expf(-fabsf(x)));
    }
    __syncthreads();

    float lmax = -1e30f;
    for (int g = t; g < NG; g += 256) {
        uchar4 id = g_idx[g];
        float w = s_sp[id.x] * s_sp[id.y] * s_sp[id.z];
        s_w[g] = w;
        lmax = fmaxf(lmax, w);
    }
#pragma unroll
    for (int o = 16; o; o >>= 1) lmax = fmaxf(lmax, __shfl_xor_sync(0xFFFFFFFFu, lmax, o));
    if ((t & 31) == 0) s_red[t >> 5] = lmax;
    __syncthreads();
    float bmax = s_red[0];
#pragma unroll
    for (int w = 1; w < 8; ++w) bmax = fmaxf(bmax, s_red[w]);
    __syncthreads();

    float lsum = 0.f;
    for (int g = t; g < NG; g += 256) {
        float e = fexp(s_w[g] - bmax);
        s_w[g] = e;
        lsum += e;
    }
#pragma unroll
    for (int o = 16; o; o >>= 1) lsum += __shfl_xor_sync(0xFFFFFFFFu, lsum, o);
    if ((t & 31) == 0) s_red[t >> 5] = lsum;
    __syncthreads();
    float bsum = 0.f;
#pragma unroll
    for (int w = 0; w < 8; ++w) bsum += s_red[w];
    float inv = 1.0f / bsum;
    __syncthreads();

    // packed coalesced fp16 store, 2 g per u32
    uint32_t* dst = (uint32_t*)(g_Wb + (long)q * KP);
    for (int g2 = t; g2 < NG / 2; g2 += 256) {
        __half2 h = __floats2half2_rn(s_w[2 * g2] * inv, s_w[2 * g2 + 1] * inv);
        dst[g2] = *(const uint32_t*)&h;
    }
}

// ---------------- kernel C: fp16 HMMA GEMM 512x512x4960, split-K=31 ----------
// BM=BN=128, BK=32, 8 warps 2(m)x4(n), cp.async double-buffered, 5 iters/CTA.
__global__ __launch_bounds__(256, 2) void k_mma() {
    __shared__ __align__(16) __half sA[2][128 * LDSW];
    __shared__ __align__(16) __half sB[2][128 * LDSW];
    const int t = threadIdx.x, lane = t & 31, wid = t >> 5;
    const int wm = wid & 1, wn = wid >> 1;
    const int m0 = blockIdx.y * 128, n0 = blockIdx.x * 128;
    const long kbase = (long)blockIdx.z * ITERS * BK;

    float acc[4][4][4];
#pragma unroll
    for (int i = 0; i < 4; ++i)
#pragma unroll
        for (int j = 0; j < 4; ++j)
#pragma unroll
            for (int v = 0; v < 4; ++v) acc[i][j][v] = 0.f;

    const int grow = t >> 2, gq = t & 3;
    const uint32_t sA0 = smem_u32(sA), sB0 = smem_u32(sB);
    const uint32_t BUFB = 128 * LDSW * 2;
    const uint32_t dA0 = sA0 + (uint32_t)((grow * LDSW + gq * 8) * 2);
    const uint32_t dA1 = dA0 + (uint32_t)(64 * LDSW * 2);
    const uint32_t dB0 = sB0 + (uint32_t)((grow * LDSW + gq * 8) * 2);
    const uint32_t dB1 = dB0 + (uint32_t)(64 * LDSW * 2);

    const int lr = lane & 15, lh = lane >> 4;
    const uint32_t aBase = sA0 + (uint32_t)(((wm * 64 + lr) * LDSW + lh * 8) * 2);
    const uint32_t bBase = sB0 + (uint32_t)(((wn * 32 + lr) * LDSW + lh * 8) * 2);

    {
        const long k0 = kbase;
        CP_ASYNC16(dA0, g_Wb  + (long)(m0 + grow)      * KP + k0 + gq * 8);
        CP_ASYNC16(dA1, g_Wb  + (long)(m0 + grow + 64) * KP + k0 + gq * 8);
        CP_ASYNC16(dB0, g_RCb + (long)(n0 + grow)      * KP + k0 + gq * 8);
        CP_ASYNC16(dB1, g_RCb + (long)(n0 + grow + 64) * KP + k0 + gq * 8);
        CP_COMMIT();
    }

#pragma unroll 1
    for (int tt = 0; tt < ITERS; ++tt) {
        if (tt + 1 < ITERS) {
            const long k0 = kbase + (long)(tt + 1) * BK;
            const uint32_t bo = ((tt + 1) & 1) * BUFB;
            CP_ASYNC16(dA0 + bo, g_Wb  + (long)(m0 + grow)      * KP + k0 + gq * 8);
            CP_ASYNC16(dA1 + bo, g_Wb  + (long)(m0 + grow + 64) * KP + k0 + gq * 8);
            CP_ASYNC16(dB0 + bo, g_RCb + (long)(n0 + grow)      * KP + k0 + gq * 8);
            CP_ASYNC16(dB1 + bo, g_RCb + (long)(n0 + grow + 64) * KP + k0 + gq * 8);
            CP_COMMIT();
            CP_WAIT(1);
        } else {
            CP_WAIT(0);
        }
        __syncthreads();

        const uint32_t bo = (tt & 1) * BUFB;
#pragma unroll
        for (int ks = 0; ks < 2; ++ks) {
            uint32_t af[4][4], bf[2][4];
#pragma unroll
            for (int mt = 0; mt < 4; ++mt)
                ldmx4(af[mt], aBase + bo + mt * (16 * LDSW * 2) + ks * 32);
#pragma unroll
            for (int np = 0; np < 2; ++np)
                ldmx4(bf[np], bBase + bo + np * (16 * LDSW * 2) + ks * 32);
#pragma unroll
            for (int mt = 0; mt < 4; ++mt)
#pragma unroll
                for (int nt = 0; nt < 4; ++nt)
                    mma_f16(acc[mt][nt], af[mt], bf[nt >> 1][nt & 1],
                            bf[nt >> 1][(nt & 1) + 2]);
        }
        __syncthreads();
    }

    __half* P = g_part + (long)blockIdx.z * OUT_ELEMS;
    const int erow = lane >> 2, ecol = (lane & 3) * 2;
#pragma unroll
    for (int mt = 0; mt < 4; ++mt)
#pragma unroll
        for (int nt = 0; nt < 4; ++nt) {
            int m = m0 + wm * 64 + mt * 16 + erow;
            int n = n0 + wn * 32 + nt * 8 + ecol;
            __half2 h0 = __floats2half2_rn(acc[mt][nt][0], acc[mt][nt][1]);
            __half2 h1 = __floats2half2_rn(acc[mt][nt][2], acc[mt][nt][3]);
            *(uint32_t*)&P[(long)m * NCOL + n]       = *(const uint32_t*)&h0;
            *(uint32_t*)&P[(long)(m + 8) * NCOL + n] = *(const uint32_t*)&h1;
        }
}

// ---------------- kernel D: reduce fp16 split-K partials + scatter -----------
__global__ void k_reduce(float* __restrict__ out) {
    int t = blockIdx.x * blockDim.x + threadIdx.x;   // half2 index
    if (t >= OUT_ELEMS / 2) return;
    const uint32_t* P = (const uint32_t*)g_part;
    float s0 = 0.f, s1 = 0.f;
#pragma unroll
    for (int j = 0; j < NSPLIT; ++j) {
        uint32_t v = P[(long)j * (OUT_ELEMS / 2) + t];
        __half2 h = *(const __half2*)&v;
        float2 f = __half22float2(h);
        s0 += f.x; s1 += f.y;
    }
    int q = t >> 8, colp = t & 255;
    int col = colp * 2;
    int b = col >> 4, f = col & 15;
    *(float2*)&out[((long)b * NQ + q) * NFILT + f] = make_float2(s0, s1);
}

// ---------------- launch -----------------------------------------------------
extern "C" void kernel_launch(void* const* d_in, const int* in_sizes, int n_in,
                              void* d_out, int out_size) {
    const float *inputs = nullptr, *logits = nullptr, *filts = nullptr;
    for (int i = 0; i < n_in; ++i) {
        if (in_sizes[i] == BATCH * N_OBJ * N_OBJ * RDIM) inputs = (const float*)d_in[i];
        else if (in_sizes[i] == NQ * N_OBJ)              logits = (const float*)d_in[i];
        else if (in_sizes[i] == NFILT * 3 * 3 * RDIM)    filts = (const float*)d_in[i];
    }
    float* out = (float*)d_out;

    k_idx<<<20, 256>>>();
    k_fused<<<128, 256>>>(inputs, filts);
    k_weights<<<NQ, 256>>>(logits);
    k_rcasm<<<dim3(20, 32), 256>>>();
    k_mma<<<dim3(4, 4, NSPLIT), 256>>>();
    k_reduce<<<(OUT_ELEMS / 2 + 255) / 256, 256>>>(out);
}

// round 15
// speedup vs baseline: 2.6106x; 1.0391x over previous
#include <cuda_runtime.h>
#include <cuda_bf16.h>
#include <cuda_fp16.h>
#include <cstdint>

#define N_OBJ 32
#define NFILT 16
#define RDIM 16
#define BATCH 32
#define NQ 512
#define NG 4960                  // C(32,3)
#define NCOL 512                 // BATCH * NFILT
#define OUT_ELEMS (NQ * NCOL)    // 262144
#define KP 4960                  // K = NG, = 155 * 32 exactly
#define NSPLIT 31
#define ITERS 5                  // 155 / 31
#define BK 32
#define LDSW 40                  // smem row stride (halves); 80B rows, ldmatrix-safe
#define GB 64                    // g per rcasm block

// ---------------- scratch (device globals) -----------------------------------
__device__ float  g_E  [3 * BATCH * 1024 * 16];   // E01,E02,E12 [e][b][xy][f]
__device__ __half g_Wb [NQ   * KP];               // A [q][k]   fp16
__device__ __half g_RCb[NCOL * KP];               // B [col][k] fp16
__device__ __half g_part[NSPLIT * OUT_ELEMS];     // fp16 split-K partials
__device__ uchar4 g_idx[NG];                      // packed combination table

// ---------------- helpers ----------------------------------------------------
__device__ __forceinline__ uint32_t smem_u32(const void* p) {
    uint32_t a;
    asm("{ .reg .u64 t; cvta.to.shared.u64 t, %1; cvt.u32.u64 %0, t; }" : "=r"(a) : "l"(p));
    return a;
}
__device__ __forceinline__ void ldmx4(uint32_t r[4], uint32_t addr) {
    asm volatile("ldmatrix.sync.aligned.m8n8.x4.shared.b16 {%0,%1,%2,%3}, [%4];"
                 : "=r"(r[0]), "=r"(r[1]), "=r"(r[2]), "=r"(r[3]) : "r"(addr));
}
__device__ __forceinline__ void mma_f16(float c[4], const uint32_t a[4],
                                        uint32_t b0, uint32_t b1) {
    asm volatile("mma.sync.aligned.m16n8k16.row.col.f32.f16.f16.f32 "
                 "{%0,%1,%2,%3}, {%4,%5,%6,%7}, {%8,%9}, {%0,%1,%2,%3};"
                 : "+f"(c[0]), "+f"(c[1]), "+f"(c[2]), "+f"(c[3])
                 : "r"(a[0]), "r"(a[1]), "r"(a[2]), "r"(a[3]), "r"(b0), "r"(b1));
}
#define CP_ASYNC16(dst, src) \
    asm volatile("cp.async.cg.shared.global [%0], [%1], 16;" :: "r"(dst), "l"(src) : "memory")
#define CP_COMMIT() asm volatile("cp.async.commit_group;" ::: "memory")
#define CP_WAIT(n)  asm volatile("cp.async.wait_group %0;" :: "n"(n) : "memory")

// FMA-pipe exp: exp(x) for x <= 0 (softmax arg), ~1e-7 rel err, no MUFU.
__device__ __forceinline__ float fexp(float x) {
    x = fmaxf(x, -80.0f);
    float t = x * 1.4426950408889634f;
    float tm = t + 12582912.0f;
    int   n  = __float_as_int(tm) - 0x4B400000;
    float r  = t - (tm - 12582912.0f);
    float p = 1.540353039338161e-4f;
    p = p * r + 1.3333558146428443e-3f;
    p = p * r + 9.618129107628477e-3f;
    p = p * r + 5.550410866482158e-2f;
    p = p * r + 2.402265069591007e-1f;
    p = p * r + 6.931471805599453e-1f;
    p = p * r + 1.0f;
    return __int_as_float(__float_as_int(p) + (n << 23));
}

// ---------------- kernel F: fused pairconv + plane combine -> E  (+ unrank) --
__global__ __launch_bounds__(256) void k_fused(const float* __restrict__ inputs,
                                               const float* __restrict__ filters) {
    __shared__ float4 s_f[9 * 16 * 4];          // [ac][d][f4]
    const int t = threadIdx.x;
#pragma unroll
    for (int u = 0; u < 9; ++u) {
        int idx = t + u * 256;                  // < 2304
        int ac = idx >> 8, rem = idx & 255;
        int d = rem >> 4, f = rem & 15;
        ((float*)s_f)[((ac * 16 + d) << 4) + f] = filters[(f * 9 + ac) * 16 + d];
    }

    const int cell = blockIdx.x * 256 + t;      // (b, xy) in [0, 32768)

    // fold in the combination unrank (first NG threads)
    if (cell < NG) {
        int r = cell, i = 0;
        for (; i < 30; ++i) { int c = (31 - i) * (30 - i) / 2; if (r < c) break; r -= c; }
        int j = i + 1;
        for (; j < 31; ++j) { int c = 31 - j; if (r < c) break; r -= c; }
        g_idx[cell] = make_uchar4((unsigned char)i, (unsigned char)j,
                                  (unsigned char)(j + 1 + r), 0);
    }
    __syncthreads();

    const int b = cell >> 10, ij = cell & 1023;
    const int x = ij >> 5, y = ij & 31;
    const float4* base = (const float4*)(inputs + (long)b * 16384);

    float4 rij[4], rji[4], rxx[4], ryy[4];
#pragma unroll
    for (int u = 0; u < 4; ++u) {
        rij[u] = base[(x * 32 + y) * 4 + u];
        rji[u] = base[(y * 32 + x) * 4 + u];
        rxx[u] = base[(x * 33) * 4 + u];
        ryy[u] = base[(y * 33) * 4 + u];
    }
    const float* fij = (const float*)rij;
    const float* fji = (const float*)rji;
    const float* fxx = (const float*)rxx;
    const float* fyy = (const float*)ryy;

#pragma unroll
    for (int e = 0; e < 3; ++e) {
        const int ps = (e == 0) ? 1 : (e == 1) ? 2 : 5;
        const int pt = (e == 0) ? 3 : (e == 1) ? 6 : 7;
        const int pd = (e == 0) ? 0 : (e == 1) ? 8 : 4;
        const float* fd = (e == 1) ? fyy : fxx;
        float4 acc[4] = { {0,0,0,0}, {0,0,0,0}, {0,0,0,0}, {0,0,0,0} };
#pragma unroll
        for (int d = 0; d < 16; ++d) {
            float a = fij[d], bb = fji[d], c = fd[d];
#pragma unroll
            for (int f4 = 0; f4 < 4; ++f4) {
                float4 v1 = s_f[(ps * 16 + d) * 4 + f4];
                float4 v2 = s_f[(pt * 16 + d) * 4 + f4];
                float4 v3 = s_f[(pd * 16 + d) * 4 + f4];
                acc[f4].x += a * v1.x + bb * v2.x + c * v3.x;
                acc[f4].y += a * v1.y + bb * v2.y + c * v3.y;
                acc[f4].z += a * v1.z + bb * v2.z + c * v3.z;
                acc[f4].w += a * v1.w + bb * v2.w + c * v3.w;
            }
        }
        float4* dst = (float4*)(g_E + ((long)(e * 32 + b) * 1024 + ij) * 16);
#pragma unroll
        for (int f4 = 0; f4 < 4; ++f4) dst[f4] = acc[f4];
    }
}

// ---------------- kernel A: assemble rel_conv -> B [col][k] fp16 -------------
// thread = (g-local, f4): 4 lanes cooperate on one g, each loads one float4
// of the three gathered 64B E rows -> coalesced 64B segments per g.
__global__ __launch_bounds__(256) void k_rcasm() {
    __shared__ __half s_t[GB][20];              // [g][f], 40B padded rows
    const int t = threadIdx.x;
    const int gl = t >> 2, f4 = t & 3;
    const int b = blockIdx.y;
    const int g = blockIdx.x * GB + gl;

    if (g < NG) {
        const uchar4 id = g_idx[g];
        const float4* e01 = (const float4*)(g_E + ((long)(0 * 32 + b) * 1024 + id.x * 32 + id.y) * 16);
        const float4* e02 = (const float4*)(g_E + ((long)(1 * 32 + b) * 1024 + id.x * 32 + id.z) * 16);
        const float4* e12 = (const float4*)(g_E + ((long)(2 * 32 + b) * 1024 + id.y * 32 + id.z) * 16);
        float4 a = e01[f4], c = e02[f4], d = e12[f4];
        float4 s = make_float4(a.x + c.x + d.x, a.y + c.y + d.y,
                               a.z + c.z + d.z, a.w + c.w + d.w);
        __half2 h0 = __floats2half2_rn(s.x, s.y);
        __half2 h1 = __floats2half2_rn(s.z, s.w);
        uint2 pack = make_uint2(*(const uint32_t*)&h0, *(const uint32_t*)&h1);
        *(uint2*)&s_t[gl][f4 * 4] = pack;       // 8B store, conflict-free
    }
    __syncthreads();

    // copy out: 16 f-rows x (GB/2) u32 words -> g_RCb[(b*16+f)][k]
    for (int it = t; it < 16 * (GB / 2); it += 256) {
        const int f = it >> 5;                  // 0..15
        const int gp = it & 31;                 // half2 index within chunk
        const int gg = blockIdx.x * GB + 2 * gp;
        if (gg >= NG) continue;
        __half2 hv;
        hv.x = s_t[2 * gp][f];
        hv.y = s_t[2 * gp + 1][f];
        *(uint32_t*)&g_RCb[(long)(b * 16 + f) * KP + gg] = *(const uint32_t*)&hv;
    }
}

// ---------------- kernel B: weights -> A [q][k] fp16 -------------------------
__global__ __launch_bounds__(256) void k_weights(const float* __restrict__ logits) {
    __shared__ float s_sp[N_OBJ];
    __shared__ float s_w[NG];
    __shared__ float s_red[8];
    const int q = blockIdx.x;
    const int t = threadIdx.x;

    if (t < N_OBJ) {
        float x = logits[q * N_OBJ + t];
        s_sp[t] = fmaxf(x, 0.f) + log1pf(expf(-fabsf(x)));
    }
    __syncthreads();

    float lmax = -1e30f;
    for (int g = t; g < NG; g += 256) {
        uchar4 id = g_idx[g];
        float w = s_sp[id.x] * s_sp[id.y] * s_sp[id.z];
        s_w[g] = w;
        lmax = fmaxf(lmax, w);
    }
#pragma unroll
    for (int o = 16; o; o >>= 1) lmax = fmaxf(lmax, __shfl_xor_sync(0xFFFFFFFFu, lmax, o));
    if ((t & 31) == 0) s_red[t >> 5] = lmax;
    __syncthreads();
    float bmax = s_red[0];
#pragma unroll
    for (int w = 1; w < 8; ++w) bmax = fmaxf(bmax, s_red[w]);
    __syncthreads();

    float lsum = 0.f;
    for (int g = t; g < NG; g += 256) {
        float e = fexp(s_w[g] - bmax);
        s_w[g] = e;
        lsum += e;
    }
#pragma unroll
    for (int o = 16; o; o >>= 1) lsum += __shfl_xor_sync(0xFFFFFFFFu, lsum, o);
    if ((t & 31) == 0) s_red[t >> 5] = lsum;
    __syncthreads();
    float bsum = 0.f;
#pragma unroll
    for (int w = 0; w < 8; ++w) bsum += s_red[w];
    float inv = 1.0f / bsum;
    __syncthreads();

    uint32_t* dst = (uint32_t*)(g_Wb + (long)q * KP);
    for (int g2 = t; g2 < NG / 2; g2 += 256) {
        __half2 h = __floats2half2_rn(s_w[2 * g2] * inv, s_w[2 * g2 + 1] * inv);
        dst[g2] = *(const uint32_t*)&h;
    }
}

// ---------------- kernel C: fp16 HMMA GEMM 512x512x4960, split-K=31 ----------
__global__ __launch_bounds__(256, 2) void k_mma() {
    __shared__ __align__(16) __half sA[2][128 * LDSW];
    __shared__ __align__(16) __half sB[2][128 * LDSW];
    const int t = threadIdx.x, lane = t & 31, wid = t >> 5;
    const int wm = wid & 1, wn = wid >> 1;
    const int m0 = blockIdx.y * 128, n0 = blockIdx.x * 128;
    const long kbase = (long)blockIdx.z * ITERS * BK;

    float acc[4][4][4];
#pragma unroll
    for (int i = 0; i < 4; ++i)
#pragma unroll
        for (int j = 0; j < 4; ++j)
#pragma unroll
            for (int v = 0; v < 4; ++v) acc[i][j][v] = 0.f;

    const int grow = t >> 2, gq = t & 3;
    const uint32_t sA0 = smem_u32(sA), sB0 = smem_u32(sB);
    const uint32_t BUFB = 128 * LDSW * 2;
    const uint32_t dA0 = sA0 + (uint32_t)((grow * LDSW + gq * 8) * 2);
    const uint32_t dA1 = dA0 + (uint32_t)(64 * LDSW * 2);
    const uint32_t dB0 = sB0 + (uint32_t)((grow * LDSW + gq * 8) * 2);
    const uint32_t dB1 = dB0 + (uint32_t)(64 * LDSW * 2);

    const int lr = lane & 15, lh = lane >> 4;
    const uint32_t aBase = sA0 + (uint32_t)(((wm * 64 + lr) * LDSW + lh * 8) * 2);
    const uint32_t bBase = sB0 + (uint32_t)(((wn * 32 + lr) * LDSW + lh * 8) * 2);

    {
        const long k0 = kbase;
        CP_ASYNC16(dA0, g_Wb  + (long)(m0 + grow)      * KP + k0 + gq * 8);
        CP_ASYNC16(dA1, g_Wb  + (long)(m0 + grow + 64) * KP + k0 + gq * 8);
        CP_ASYNC16(dB0, g_RCb + (long)(n0 + grow)      * KP + k0 + gq * 8);
        CP_ASYNC16(dB1, g_RCb + (long)(n0 + grow + 64) * KP + k0 + gq * 8);
        CP_COMMIT();
    }

#pragma unroll 1
    for (int tt = 0; tt < ITERS; ++tt) {
        if (tt + 1 < ITERS) {
            const long k0 = kbase + (long)(tt + 1) * BK;
            const uint32_t bo = ((tt + 1) & 1) * BUFB;
            CP_ASYNC16(dA0 + bo, g_Wb  + (long)(m0 + grow)      * KP + k0 + gq * 8);
            CP_ASYNC16(dA1 + bo, g_Wb  + (long)(m0 + grow + 64) * KP + k0 + gq * 8);
            CP_ASYNC16(dB0 + bo, g_RCb + (long)(n0 + grow)      * KP + k0 + gq * 8);
            CP_ASYNC16(dB1 + bo, g_RCb + (long)(n0 + grow + 64) * KP + k0 + gq * 8);
            CP_COMMIT();
            CP_WAIT(1);
        } else {
            CP_WAIT(0);
        }
        __syncthreads();

        const uint32_t bo = (tt & 1) * BUFB;
#pragma unroll
        for (int ks = 0; ks < 2; ++ks) {
            uint32_t af[4][4], bf[2][4];
#pragma unroll
            for (int mt = 0; mt < 4; ++mt)
                ldmx4(af[mt], aBase + bo + mt * (16 * LDSW * 2) + ks * 32);
#pragma unroll
            for (int np = 0; np < 2; ++np)
                ldmx4(bf[np], bBase + bo + np * (16 * LDSW * 2) + ks * 32);
#pragma unroll
            for (int mt = 0; mt < 4; ++mt)
#pragma unroll
                for (int nt = 0; nt < 4; ++nt)
                    mma_f16(acc[mt][nt], af[mt], bf[nt >> 1][nt & 1],
                            bf[nt >> 1][(nt & 1) + 2]);
        }
        __syncthreads();
    }

    __half* P = g_part + (long)blockIdx.z * OUT_ELEMS;
    const int erow = lane >> 2, ecol = (lane & 3) * 2;
#pragma unroll
    for (int mt = 0; mt < 4; ++mt)
#pragma unroll
        for (int nt = 0; nt < 4; ++nt) {
            int m = m0 + wm * 64 + mt * 16 + erow;
            int n = n0 + wn * 32 + nt * 8 + ecol;
            __half2 h0 = __floats2half2_rn(acc[mt][nt][0], acc[mt][nt][1]);
            __half2 h1 = __floats2half2_rn(acc[mt][nt][2], acc[mt][nt][3]);
            *(uint32_t*)&P[(long)m * NCOL + n]       = *(const uint32_t*)&h0;
            *(uint32_t*)&P[(long)(m + 8) * NCOL + n] = *(const uint32_t*)&h1;
        }
}

// ---------------- kernel D: reduce fp16 split-K partials + scatter -----------
__global__ void k_reduce(float* __restrict__ out) {
    int t = blockIdx.x * blockDim.x + threadIdx.x;   // half2 index
    if (t >= OUT_ELEMS / 2) return;
    const uint32_t* P = (const uint32_t*)g_part;
    float s0 = 0.f, s1 = 0.f;
#pragma unroll
    for (int j = 0; j < NSPLIT; ++j) {
        uint32_t v = P[(long)j * (OUT_ELEMS / 2) + t];
        __half2 h = *(const __half2*)&v;
        float2 f = __half22float2(h);
        s0 += f.x; s1 += f.y;
    }
    int q = t >> 8, colp = t & 255;
    int col = colp * 2;
    int b = col >> 4, f = col & 15;
    *(float2*)&out[((long)b * NQ + q) * NFILT + f] = make_float2(s0, s1);
}

// ---------------- launch -----------------------------------------------------
extern "C" void kernel_launch(void* const* d_in, const int* in_sizes, int n_in,
                              void* d_out, int out_size) {
    const float *inputs = nullptr, *logits = nullptr, *filts = nullptr;
    for (int i = 0; i < n_in; ++i) {
        if (in_sizes[i] == BATCH * N_OBJ * N_OBJ * RDIM) inputs = (const float*)d_in[i];
        else if (in_sizes[i] == NQ * N_OBJ)              logits = (const float*)d_in[i];
        else if (in_sizes[i] == NFILT * 3 * 3 * RDIM)    filts = (const float*)d_in[i];
    }
    float* out = (float*)d_out;

    k_fused<<<128, 256>>>(inputs, filts);
    k_weights<<<NQ, 256>>>(logits);
    k_rcasm<<<dim3((NG + GB - 1) / GB, 32), 256>>>();
    k_mma<<<dim3(4, 4, NSPLIT), 256>>>();
    k_reduce<<<(OUT_ELEMS / 2 + 255) / 256, 256>>>(out);
}

// round 16
// speedup vs baseline: 2.7242x; 1.0435x over previous
#include <cuda_runtime.h>
#include <cuda_bf16.h>
#include <cuda_fp16.h>
#include <cstdint>

#define N_OBJ 32
#define NFILT 16
#define RDIM 16
#define BATCH 32
#define NQ 512
#define NG 4960                  // C(32,3)
#define NCOL 512                 // BATCH * NFILT
#define OUT_ELEMS (NQ * NCOL)    // 262144
#define KP 5120                  // padded K (zeros beyond NG), = 160 * 32
#define NSPLIT 16
#define ITERS 10                 // 160 / 16
#define BK 32
#define LDSW 40                  // smem row stride (halves); 80B rows, ldmatrix-safe
#define GB 64                    // g per rcasm block

// ---------------- scratch (device globals) -----------------------------------
__device__ float  g_E  [3 * BATCH * 1024 * 16];   // E01,E02,E12 [e][b][xy][f]
__device__ __half g_Wb [NQ   * KP];               // A [q][k]   fp16 (padded)
__device__ __half g_RCb[NCOL * KP];               // B [col][k] fp16 (padded)
__device__ __half g_part[NSPLIT * OUT_ELEMS];     // fp16 split-K partials
__device__ uchar4 g_idx[NG];                      // packed combination table

// ---------------- helpers ----------------------------------------------------
__device__ __forceinline__ uint32_t smem_u32(const void* p) {
    uint32_t a;
    asm("{ .reg .u64 t; cvta.to.shared.u64 t, %1; cvt.u32.u64 %0, t; }" : "=r"(a) : "l"(p));
    return a;
}
__device__ __forceinline__ void ldmx4(uint32_t r[4], uint32_t addr) {
    asm volatile("ldmatrix.sync.aligned.m8n8.x4.shared.b16 {%0,%1,%2,%3}, [%4];"
                 : "=r"(r[0]), "=r"(r[1]), "=r"(r[2]), "=r"(r[3]) : "r"(addr));
}
__device__ __forceinline__ void mma_f16(float c[4], const uint32_t a[4],
                                        uint32_t b0, uint32_t b1) {
    asm volatile("mma.sync.aligned.m16n8k16.row.col.f32.f16.f16.f32 "
                 "{%0,%1,%2,%3}, {%4,%5,%6,%7}, {%8,%9}, {%0,%1,%2,%3};"
                 : "+f"(c[0]), "+f"(c[1]), "+f"(c[2]), "+f"(c[3])
                 : "r"(a[0]), "r"(a[1]), "r"(a[2]), "r"(a[3]), "r"(b0), "r"(b1));
}
#define CP_ASYNC16(dst, src) \
    asm volatile("cp.async.cg.shared.global [%0], [%1], 16;" :: "r"(dst), "l"(src) : "memory")
#define CP_COMMIT() asm volatile("cp.async.commit_group;" ::: "memory")
#define CP_WAIT(n)  asm volatile("cp.async.wait_group %0;" :: "n"(n) : "memory")

// FMA-pipe exp: exp(x) for x <= 0 (softmax arg), ~1e-7 rel err, no MUFU.
__device__ __forceinline__ float fexp(float x) {
    x = fmaxf(x, -80.0f);
    float t = x * 1.4426950408889634f;
    float tm = t + 12582912.0f;
    int   n  = __float_as_int(tm) - 0x4B400000;
    float r  = t - (tm - 12582912.0f);
    float p = 1.540353039338161e-4f;
    p = p * r + 1.3333558146428443e-3f;
    p = p * r + 9.618129107628477e-3f;
    p = p * r + 5.550410866482158e-2f;
    p = p * r + 2.402265069591007e-1f;
    p = p * r + 6.931471805599453e-1f;
    p = p * r + 1.0f;
    return __int_as_float(__float_as_int(p) + (n << 23));
}

// ---------------- kernel F: fused pairconv + plane combine -> E  (+ unrank) --
__global__ __launch_bounds__(256) void k_fused(const float* __restrict__ inputs,
                                               const float* __restrict__ filters) {
    __shared__ float4 s_f[9 * 16 * 4];          // [ac][d][f4]
    const int t = threadIdx.x;
#pragma unroll
    for (int u = 0; u < 9; ++u) {
        int idx = t + u * 256;                  // < 2304
        int ac = idx >> 8, rem = idx & 255;
        int d = rem >> 4, f = rem & 15;
        ((float*)s_f)[((ac * 16 + d) << 4) + f] = filters[(f * 9 + ac) * 16 + d];
    }

    const int cell = blockIdx.x * 256 + t;      // (b, xy) in [0, 32768)

    if (cell < NG) {                            // fold in the combination unrank
        int r = cell, i = 0;
        for (; i < 30; ++i) { int c = (31 - i) * (30 - i) / 2; if (r < c) break; r -= c; }
        int j = i + 1;
        for (; j < 31; ++j) { int c = 31 - j; if (r < c) break; r -= c; }
        g_idx[cell] = make_uchar4((unsigned char)i, (unsigned char)j,
                                  (unsigned char)(j + 1 + r), 0);
    }
    __syncthreads();

    const int b = cell >> 10, ij = cell & 1023;
    const int x = ij >> 5, y = ij & 31;
    const float4* base = (const float4*)(inputs + (long)b * 16384);

    float4 rij[4], rji[4], rxx[4], ryy[4];
#pragma unroll
    for (int u = 0; u < 4; ++u) {
        rij[u] = base[(x * 32 + y) * 4 + u];
        rji[u] = base[(y * 32 + x) * 4 + u];
        rxx[u] = base[(x * 33) * 4 + u];
        ryy[u] = base[(y * 33) * 4 + u];
    }
    const float* fij = (const float*)rij;
    const float* fji = (const float*)rji;
    const float* fxx = (const float*)rxx;
    const float* fyy = (const float*)ryy;

#pragma unroll
    for (int e = 0; e < 3; ++e) {
        const int ps = (e == 0) ? 1 : (e == 1) ? 2 : 5;
        const int pt = (e == 0) ? 3 : (e == 1) ? 6 : 7;
        const int pd = (e == 0) ? 0 : (e == 1) ? 8 : 4;
        const float* fd = (e == 1) ? fyy : fxx;
        float4 acc[4] = { {0,0,0,0}, {0,0,0,0}, {0,0,0,0}, {0,0,0,0} };
#pragma unroll
        for (int d = 0; d < 16; ++d) {
            float a = fij[d], bb = fji[d], c = fd[d];
#pragma unroll
            for (int f4 = 0; f4 < 4; ++f4) {
                float4 v1 = s_f[(ps * 16 + d) * 4 + f4];
                float4 v2 = s_f[(pt * 16 + d) * 4 + f4];
                float4 v3 = s_f[(pd * 16 + d) * 4 + f4];
                acc[f4].x += a * v1.x + bb * v2.x + c * v3.x;
                acc[f4].y += a * v1.y + bb * v2.y + c * v3.y;
                acc[f4].z += a * v1.z + bb * v2.z + c * v3.z;
                acc[f4].w += a * v1.w + bb * v2.w + c * v3.w;
            }
        }
        float4* dst = (float4*)(g_E + ((long)(e * 32 + b) * 1024 + ij) * 16);
#pragma unroll
        for (int f4 = 0; f4 < 4; ++f4) dst[f4] = acc[f4];
    }
}

// ---------------- kernel A: assemble rel_conv -> B [col][k] fp16 (padded) ----
__global__ __launch_bounds__(256) void k_rcasm() {
    __shared__ __half s_t[GB][20];              // [g][f], 40B padded rows
    const int t = threadIdx.x;
    const int gl = t >> 2, f4 = t & 3;
    const int b = blockIdx.y;
    const int g = blockIdx.x * GB + gl;

    if (g < NG) {
        const uchar4 id = g_idx[g];
        const float4* e01 = (const float4*)(g_E + ((long)(0 * 32 + b) * 1024 + id.x * 32 + id.y) * 16);
        const float4* e02 = (const float4*)(g_E + ((long)(1 * 32 + b) * 1024 + id.x * 32 + id.z) * 16);
        const float4* e12 = (const float4*)(g_E + ((long)(2 * 32 + b) * 1024 + id.y * 32 + id.z) * 16);
        float4 a = e01[f4], c = e02[f4], d = e12[f4];
        float4 s = make_float4(a.x + c.x + d.x, a.y + c.y + d.y,
                               a.z + c.z + d.z, a.w + c.w + d.w);
        __half2 h0 = __floats2half2_rn(s.x, s.y);
        __half2 h1 = __floats2half2_rn(s.z, s.w);
        uint2 pack = make_uint2(*(const uint32_t*)&h0, *(const uint32_t*)&h1);
        *(uint2*)&s_t[gl][f4 * 4] = pack;       // 8B store, conflict-free
    } else {
        *(uint2*)&s_t[gl][f4 * 4] = make_uint2(0u, 0u);   // K pad = zeros
    }
    __syncthreads();

    // copy out: 16 f-rows x (GB/2) u32 words -> g_RCb[(b*16+f)][k]
    for (int it = t; it < 16 * (GB / 2); it += 256) {
        const int f = it >> 5;                  // 0..15
        const int gp = it & 31;                 // half2 index within chunk
        const int gg = blockIdx.x * GB + 2 * gp;
        __half2 hv;
        hv.x = s_t[2 * gp][f];
        hv.y = s_t[2 * gp + 1][f];
        *(uint32_t*)&g_RCb[(long)(b * 16 + f) * KP + gg] = *(const uint32_t*)&hv;
    }
}

// ---------------- kernel B: weights -> A [q][k] fp16 (padded) ----------------
__global__ __launch_bounds__(256) void k_weights(const float* __restrict__ logits) {
    __shared__ float s_sp[N_OBJ];
    __shared__ float s_w[NG];
    __shared__ float s_red[8];
    const int q = blockIdx.x;
    const int t = threadIdx.x;

    if (t < N_OBJ) {
        float x = logits[q * N_OBJ + t];
        s_sp[t] = fmaxf(x, 0.f) + log1pf(expf(-fabsf(x)));
    }
    __syncthreads();

    float lmax = -1e30f;
    for (int g = t; g < NG; g += 256) {
        uchar4 id = g_idx[g];
        float w = s_sp[id.x] * s_sp[id.y] * s_sp[id.z];
        s_w[g] = w;
        lmax = fmaxf(lmax, w);
    }
#pragma unroll
    for (int o = 16; o; o >>= 1) lmax = fmaxf(lmax, __shfl_xor_sync(0xFFFFFFFFu, lmax, o));
    if ((t & 31) == 0) s_red[t >> 5] = lmax;
    __syncthreads();
    float bmax = s_red[0];
#pragma unroll
    for (int w = 1; w < 8; ++w) bmax = fmaxf(bmax, s_red[w]);
    __syncthreads();

    float lsum = 0.f;
    for (int g = t; g < NG; g += 256) {
        float e = fexp(s_w[g] - bmax);
        s_w[g] = e;
        lsum += e;
    }
#pragma unroll
    for (int o = 16; o; o >>= 1) lsum += __shfl_xor_sync(0xFFFFFFFFu, lsum, o);
    if ((t & 31) == 0) s_red[t >> 5] = lsum;
    __syncthreads();
    float bsum = 0.f;
#pragma unroll
    for (int w = 0; w < 8; ++w) bsum += s_red[w];
    float inv = 1.0f / bsum;
    __syncthreads();

    uint32_t* dst = (uint32_t*)(g_Wb + (long)q * KP);
    for (int g2 = t; g2 < KP / 2; g2 += 256) {
        float w0 = (2 * g2     < NG) ? s_w[2 * g2]     * inv : 0.f;
        float w1 = (2 * g2 + 1 < NG) ? s_w[2 * g2 + 1] * inv : 0.f;
        __half2 h = __floats2half2_rn(w0, w1);
        dst[g2] = *(const uint32_t*)&h;
    }
}

// ---------------- kernel C: fp16 HMMA GEMM 512x512x5120, split-K=16 ----------
// BM=BN=128, BK=32, 8 warps 2(m)x4(n). 3-stage cp.async, ONE sync per iter.
// 256 CTAs = one full wave @2 CTAs/SM.
__global__ __launch_bounds__(256, 2) void k_mma() {
    __shared__ __align__(16) __half sA[3][128 * LDSW];
    __shared__ __align__(16) __half sB[3][128 * LDSW];
    const int t = threadIdx.x, lane = t & 31, wid = t >> 5;
    const int wm = wid & 1, wn = wid >> 1;
    const int m0 = blockIdx.y * 128, n0 = blockIdx.x * 128;
    const long kbase = (long)blockIdx.z * ITERS * BK;

    float acc[4][4][4];
#pragma unroll
    for (int i = 0; i < 4; ++i)
#pragma unroll
        for (int j = 0; j < 4; ++j)
#pragma unroll
            for (int v = 0; v < 4; ++v) acc[i][j][v] = 0.f;

    const int grow = t >> 2, gq = t & 3;
    const uint32_t sA0 = smem_u32(sA), sB0 = smem_u32(sB);
    const uint32_t BUFB = 128 * LDSW * 2;
    const uint32_t dA0 = sA0 + (uint32_t)((grow * LDSW + gq * 8) * 2);
    const uint32_t dA1 = dA0 + (uint32_t)(64 * LDSW * 2);
    const uint32_t dB0 = sB0 + (uint32_t)((grow * LDSW + gq * 8) * 2);
    const uint32_t dB1 = dB0 + (uint32_t)(64 * LDSW * 2);

    const int lr = lane & 15, lh = lane >> 4;
    const uint32_t aBase = sA0 + (uint32_t)(((wm * 64 + lr) * LDSW + lh * 8) * 2);
    const uint32_t bBase = sB0 + (uint32_t)(((wn * 32 + lr) * LDSW + lh * 8) * 2);

    auto load_tile = [&](int stage, int tt) {
        const long k0 = kbase + (long)tt * BK;
        const uint32_t bo = (uint32_t)stage * BUFB;
        CP_ASYNC16(dA0 + bo, g_Wb  + (long)(m0 + grow)      * KP + k0 + gq * 8);
        CP_ASYNC16(dA1 + bo, g_Wb  + (long)(m0 + grow + 64) * KP + k0 + gq * 8);
        CP_ASYNC16(dB0 + bo, g_RCb + (long)(n0 + grow)      * KP + k0 + gq * 8);
        CP_ASYNC16(dB1 + bo, g_RCb + (long)(n0 + grow + 64) * KP + k0 + gq * 8);
        CP_COMMIT();
    };

    load_tile(0, 0);
    load_tile(1, 1);

    int stage = 0, pstage = 2;
#pragma unroll 1
    for (int tt = 0; tt < ITERS; ++tt) {
        if (tt + 1 < ITERS) { CP_WAIT(1); } else { CP_WAIT(0); }
        __syncthreads();                          // iter tt-1 readers done + tile tt ready
        if (tt + 2 < ITERS) load_tile(pstage, tt + 2);

        const uint32_t bo = (uint32_t)stage * BUFB;
#pragma unroll
        for (int ks = 0; ks < 2; ++ks) {
            uint32_t af[4][4], bf[2][4];
#pragma unroll
            for (int mt = 0; mt < 4; ++mt)
                ldmx4(af[mt], aBase + bo + mt * (16 * LDSW * 2) + ks * 32);
#pragma unroll
            for (int np = 0; np < 2; ++np)
                ldmx4(bf[np], bBase + bo + np * (16 * LDSW * 2) + ks * 32);
#pragma unroll
            for (int mt = 0; mt < 4; ++mt)
#pragma unroll
                for (int nt = 0; nt < 4; ++nt)
                    mma_f16(acc[mt][nt], af[mt], bf[nt >> 1][nt & 1],
                            bf[nt >> 1][(nt & 1) + 2]);
        }
        stage = (stage + 1 == 3) ? 0 : stage + 1;
        pstage = (pstage + 1 == 3) ? 0 : pstage + 1;
    }

    __half* P = g_part + (long)blockIdx.z * OUT_ELEMS;
    const int erow = lane >> 2, ecol = (lane & 3) * 2;
#pragma unroll
    for (int mt = 0; mt < 4; ++mt)
#pragma unroll
        for (int nt = 0; nt < 4; ++nt) {
            int m = m0 + wm * 64 + mt * 16 + erow;
            int n = n0 + wn * 32 + nt * 8 + ecol;
            __half2 h0 = __floats2half2_rn(acc[mt][nt][0], acc[mt][nt][1]);
            __half2 h1 = __floats2half2_rn(acc[mt][nt][2], acc[mt][nt][3]);
            *(uint32_t*)&P[(long)m * NCOL + n]       = *(const uint32_t*)&h0;
            *(uint32_t*)&P[(long)(m + 8) * NCOL + n] = *(const uint32_t*)&h1;
        }
}

// ---------------- kernel D: reduce fp16 split-K partials + scatter -----------
__global__ void k_reduce(float* __restrict__ out) {
    int t = blockIdx.x * blockDim.x + threadIdx.x;   // half2 index
    if (t >= OUT_ELEMS / 2) return;
    const uint32_t* P = (const uint32_t*)g_part;
    float s0 = 0.f, s1 = 0.f;
#pragma unroll
    for (int j = 0; j < NSPLIT; ++j) {
        uint32_t v = P[(long)j * (OUT_ELEMS / 2) + t];
        __half2 h = *(const __half2*)&v;
        float2 f = __half22float2(h);
        s0 += f.x; s1 += f.y;
    }
    int q = t >> 8, colp = t & 255;
    int col = colp * 2;
    int b = col >> 4, f = col & 15;
    *(float2*)&out[((long)b * NQ + q) * NFILT + f] = make_float2(s0, s1);
}

// ---------------- launch -----------------------------------------------------
extern "C" void kernel_launch(void* const* d_in, const int* in_sizes, int n_in,
                              void* d_out, int out_size) {
    const float *inputs = nullptr, *logits = nullptr, *filts = nullptr;
    for (int i = 0; i < n_in; ++i) {
        if (in_sizes[i] == BATCH * N_OBJ * N_OBJ * RDIM) inputs = (const float*)d_in[i];
        else if (in_sizes[i] == NQ * N_OBJ)              logits = (const float*)d_in[i];
        else if (in_sizes[i] == NFILT * 3 * 3 * RDIM)    filts = (const float*)d_in[i];
    }
    float* out = (float*)d_out;

    k_fused<<<128, 256>>>(inputs, filts);
    k_weights<<<NQ, 256>>>(logits);
    k_rcasm<<<dim3(KP / GB, 32), 256>>>();
    k_mma<<<dim3(4, 4, NSPLIT), 256>>>();
    k_reduce<<<(OUT_ELEMS / 2 + 255) / 256, 256>>>(out);
}